// round 12
// baseline (speedup 1.0000x reference)
#include <cuda_runtime.h>
#include <cuda_fp16.h>
#include <math.h>

#define Bb 16
#define Ss 128
#define Nn 64
#define Ee 128
#define Hh 128
#define Ll 32

// ---------------------------------------------------------------------------
// Device-global scratch
// ---------------------------------------------------------------------------
__device__ float g_Xg[(size_t)2 * Bb * Ss * 4 * Hh];   // (dir,b,t,512)
__device__ float g_Xl[(size_t)2 * Bb * Ss * Hh];       // (dir,b,t,128)
__device__ float g_Wg[(size_t)2 * Bb * Nn * 3 * Hh];   // (dir,b,n,384)
__device__ __half g_Wwh16[(size_t)2 * 128 * 384];      // (dir, (j8*384+k)*8+i)
__device__ __half g_Wlc16[(size_t)2 * 128 * 128];      // (dir, (j8*128+k)*8+i)
__device__ float g_feats[(size_t)Bb * Ss * 2 * Hh];
__device__ float g_logits[(size_t)Bb * Ss * Ll];
__device__ float g_pb[Bb];

// fast transcendentals (~2 ulp; tolerance is 1e-3)
__device__ __forceinline__ float sigf(float x) {
    return __fdividef(1.f, 1.f + __expf(-x));
}
__device__ __forceinline__ float tanhfast(float x) {
    return 1.f - 2.f * __fdividef(1.f, __expf(2.f * x) + 1.f);
}

// accumulate 8 fp16 weights (one 16B quad = rows 8j..8j+7) against 8 fp32 h
__device__ __forceinline__ void dot8acc(float& acc, float4 hA, float4 hB, uint4 w) {
    float2 f0 = __half22float2(*reinterpret_cast<const __half2*>(&w.x));
    float2 f1 = __half22float2(*reinterpret_cast<const __half2*>(&w.y));
    float2 f2 = __half22float2(*reinterpret_cast<const __half2*>(&w.z));
    float2 f3 = __half22float2(*reinterpret_cast<const __half2*>(&w.w));
    acc = fmaf(hA.x, f0.x, acc); acc = fmaf(hA.y, f0.y, acc);
    acc = fmaf(hA.z, f1.x, acc); acc = fmaf(hA.w, f1.y, acc);
    acc = fmaf(hB.x, f2.x, acc); acc = fmaf(hB.y, f2.y, acc);
    acc = fmaf(hB.z, f3.x, acc); acc = fmaf(hB.w, f3.y, acc);
}

__device__ __forceinline__ __half2 u2h2(unsigned int v) {
    return *reinterpret_cast<const __half2*>(&v);
}

// ---------------------------------------------------------------------------
// Prep: pack Wwh/Wlc into fp16 8-row-quad layouts
// ---------------------------------------------------------------------------
__global__ void prep_pack_kernel(const float* __restrict__ fWwh,
                                 const float* __restrict__ rWwh,
                                 const float* __restrict__ fWlc,
                                 const float* __restrict__ rWlc)
{
    int which = blockIdx.y;
    int idx = blockIdx.x * 256 + threadIdx.x;
    if (which < 2) {
        const float* in = which ? rWwh : fWwh;
        __half* out = g_Wwh16 + (size_t)which * 128 * 384;
        if (idx < 128 * 384) {
            int j = idx / 384, k = idx - j * 384;
            out[((size_t)(j >> 3) * 384 + k) * 8 + (j & 7)] = __float2half(in[idx]);
        }
    } else {
        const float* in = (which == 3) ? rWlc : fWlc;
        __half* out = g_Wlc16 + (size_t)(which - 2) * 128 * 128;
        if (idx < 128 * 128) {
            int j = idx >> 7, k = idx & 127;
            out[((size_t)(j >> 3) * 128 + k) * 8 + (j & 7)] = __float2half(in[idx]);
        }
    }
}

// ---------------------------------------------------------------------------
// Fused char-side gather GEMM
// ---------------------------------------------------------------------------
__global__ void __launch_bounds__(256) char_gather_kernel(
    const float* __restrict__ emb, const int* __restrict__ ids,
    const float* __restrict__ fWcx, const float* __restrict__ rWcx,
    const float* __restrict__ fWlx, const float* __restrict__ rWlx,
    const float* __restrict__ fbc, const float* __restrict__ rbc,
    const float* __restrict__ fbl, const float* __restrict__ rbl)
{
    __shared__ float xs[8][128];
    int b = blockIdx.x, r0 = blockIdx.y * 8, tid = threadIdx.x;

    for (int idx = tid; idx < 8 * 128; idx += 256) {
        int r = idx >> 7, e = idx & 127;
        int id = ids[b * Ss + r0 + r];
        xs[r][e] = emb[(size_t)id * 128 + e];
    }
    __syncthreads();

    const float* wp[5];
    float bias[5];
    float* op[5];
    int ostep[5];

    wp[0] = fWcx + tid;        bias[0] = fbc[tid];
    wp[1] = fWcx + tid + 256;  bias[1] = fbc[tid + 256];
    op[0] = g_Xg + ((size_t)b * Ss + r0) * 512 + tid;
    op[1] = op[0] + 256;
    ostep[0] = ostep[1] = 512;
    wp[2] = rWcx + tid;        bias[2] = rbc[tid];
    wp[3] = rWcx + tid + 256;  bias[3] = rbc[tid + 256];
    op[2] = g_Xg + ((size_t)(Bb + b) * Ss + (Ss - 1 - r0)) * 512 + tid;
    op[3] = op[2] + 256;
    ostep[2] = ostep[3] = -512;
    if (tid < 128) {
        wp[4] = fWlx + tid; bias[4] = fbl[tid];
        op[4] = g_Xl + ((size_t)b * Ss + r0) * 128 + tid;
        ostep[4] = 128;
    } else {
        int c = tid - 128;
        wp[4] = rWlx + c; bias[4] = rbl[c];
        op[4] = g_Xl + ((size_t)(Bb + b) * Ss + (Ss - 1 - r0)) * 128 + c;
        ostep[4] = -128;
    }

    float acc[8][5];
#pragma unroll
    for (int r = 0; r < 8; r++)
#pragma unroll
        for (int s = 0; s < 5; s++) acc[r][s] = 0.f;

    for (int e = 0; e < 128; e++) {
        float w0 = wp[0][(size_t)e * 512];
        float w1 = wp[1][(size_t)e * 512];
        float w2 = wp[2][(size_t)e * 512];
        float w3 = wp[3][(size_t)e * 512];
        float w4 = wp[4][(size_t)e * 128];
#pragma unroll
        for (int r = 0; r < 8; r++) {
            float x = xs[r][e];
            acc[r][0] = fmaf(x, w0, acc[r][0]);
            acc[r][1] = fmaf(x, w1, acc[r][1]);
            acc[r][2] = fmaf(x, w2, acc[r][2]);
            acc[r][3] = fmaf(x, w3, acc[r][3]);
            acc[r][4] = fmaf(x, w4, acc[r][4]);
        }
    }

#pragma unroll
    for (int r = 0; r < 8; r++)
#pragma unroll
        for (int s = 0; s < 5; s++)
            op[s][(long)r * ostep[s]] = acc[r][s] + bias[s];
}

// ---------------------------------------------------------------------------
// Fused kb-side gather GEMM
// ---------------------------------------------------------------------------
__global__ void __launch_bounds__(256) kb_gather_kernel(
    const float* __restrict__ emb, const int* __restrict__ ids,
    const float* __restrict__ fW, const float* __restrict__ rW,
    const float* __restrict__ fb, const float* __restrict__ rb)
{
    __shared__ float xs[8][128];
    int b = blockIdx.x, r0 = blockIdx.y * 8, tid = threadIdx.x;

    for (int idx = tid; idx < 8 * 128; idx += 256) {
        int r = idx >> 7, e = idx & 127;
        int id = ids[b * Nn + r0 + r];
        xs[r][e] = emb[(size_t)id * 128 + e];
    }
    __syncthreads();

    const float* wp[3];
    float bias[3];
    float* op[3];
#pragma unroll
    for (int s = 0; s < 3; s++) {
        int c = tid + 256 * s;
        if (c < 384) {
            wp[s] = fW + c; bias[s] = fb[c];
            op[s] = g_Wg + ((size_t)b * Nn + r0) * 384 + c;
        } else {
            int c2 = c - 384;
            wp[s] = rW + c2; bias[s] = rb[c2];
            op[s] = g_Wg + ((size_t)(Bb + b) * Nn + r0) * 384 + c2;
        }
    }

    float acc[8][3];
#pragma unroll
    for (int r = 0; r < 8; r++)
#pragma unroll
        for (int s = 0; s < 3; s++) acc[r][s] = 0.f;

    for (int e = 0; e < 128; e++) {
        float w0 = wp[0][(size_t)e * 384];
        float w1 = wp[1][(size_t)e * 384];
        float w2 = wp[2][(size_t)e * 384];
#pragma unroll
        for (int r = 0; r < 8; r++) {
            float x = xs[r][e];
            acc[r][0] = fmaf(x, w0, acc[r][0]);
            acc[r][1] = fmaf(x, w1, acc[r][1]);
            acc[r][2] = fmaf(x, w2, acc[r][2]);
        }
    }

#pragma unroll
    for (int r = 0; r < 8; r++)
#pragma unroll
        for (int s = 0; s < 3; s++)
            op[s][(size_t)r * 384] = acc[r][s] + bias[s];
}

// ---------------------------------------------------------------------------
// Lattice LSTM (R11 structure; char weights split 96 rows regs / 32 rows smem
// to eliminate register spills; Wlc read from global with __ldg).
//   threads 0-511  : HFMA2 char matvec; tid<128 also do the cell update.
//   threads 512-639: free-running word pipeline.
// ---------------------------------------------------------------------------
#define NTHR 640

// smem BYTE offsets (all 16B aligned)
#define OFF_WWH   0                    // 98304
#define OFF_WCHT  98304                // 32768 (Wch rows 96..127, fp16 quads)
#define OFF_H32   131072               // 8*128 f32 = 4096
#define OFF_C32   135168               // 4096
#define OFF_H2    139264               // 8*128 fp16 = 2048
#define OFF_G     141312               // 512 f32 = 2048
#define OFF_CWS   143360               // 64*128 f32 = 32768
#define OFF_EWS   176128               // 32768
#define OFF_INT   208896               // 451 ints
#define SMEM_LAT  210704

__global__ void __launch_bounds__(NTHR, 1) lattice_kernel(
    const float* __restrict__ Wch_f, const float* __restrict__ Wch_r,
    const int* __restrict__ word_begin, const int* __restrict__ word_len,
    const int* __restrict__ seqlen)
{
    extern __shared__ char smraw[];
    __half* wwh_h   = (__half*)(smraw + OFF_WWH);
    __half2* wcht   = (__half2*)(smraw + OFF_WCHT);   // [(q*512+c)*4 + j]
    float* h_ring   = (float*)(smraw + OFF_H32);
    float* c_ring   = (float*)(smraw + OFF_C32);
    __half* h2r     = (__half*)(smraw + OFF_H2);
    float* gates    = (float*)(smraw + OFF_G);
    float* cw_store = (float*)(smraw + OFF_CWS);
    float* ew_store = (float*)(smraw + OFF_EWS);
    int* ip        = (int*)(smraw + OFF_INT);
    int* w_beg     = ip;            // 64
    int* w_end     = ip + 64;       // 64
    int* el_start  = ip + 128;      // 129
    int* el_idx    = ip + 257;      // 64
    int* cur       = ip + 321;      // 128
    volatile int* step_flag  = (volatile int*)(ip + 449);
    volatile int* words_done = (volatile int*)(ip + 450);

    int dirb = blockIdx.x;
    int dir  = dirb / Bb;
    int b    = dirb - dir * Bb;
    int tid  = threadIdx.x;
    int sl   = seqlen[b];

    const float* Wch  = dir ? Wch_r : Wch_f;
    const float* Xg_b = g_Xg + (size_t)dirb * Ss * 512;
    const float* Xl_b = g_Xl + (size_t)dirb * Ss * 128;
    const float* Wg_b = g_Wg + (size_t)dirb * Nn * 384;

    // copy prepacked Wwh fp16 into smem (Wlc stays in global now)
    {
        const uint4* src = (const uint4*)(g_Wwh16 + (size_t)dir * 128 * 384);
        uint4* dst = (uint4*)wwh_h;
        for (int i = tid; i < 128 * 384 / 8; i += NTHR) dst[i] = src[i];
    }
    // Wch rows 96..127 -> fp16 quad bank in smem
    // wcht[(q*512+c)*4 + j] = half2(Wch[96+8q+2j][c], Wch[96+8q+2j+1][c])
    for (int i = tid; i < 4 * 512 * 4; i += NTHR) {
        int j = i & 3;
        int c = (i >> 2) & 511;
        int q = i >> 11;
        int r0 = 96 + 8 * q + 2 * j;
        wcht[i] = __floats2half2_rn(Wch[(size_t)r0 * 512 + c],
                                    Wch[(size_t)(r0 + 1) * 512 + c]);
    }

    // Wch rows 0..95 for column tid -> 48 half2 regs (char threads)
    __half2 wh[48];
    if (tid < 512) {
#pragma unroll
        for (int j = 0; j < 48; j++)
            wh[j] = __floats2half2_rn(Wch[(size_t)(2 * j) * 512 + tid],
                                      Wch[(size_t)(2 * j + 1) * 512 + tid]);
    }

    int t0 = dir ? (Ss - sl) : 0;
    int t1 = dir ? Ss : sl;

    if (tid < 128) {
        int s0 = (t0 & 7) * Hh;
        h_ring[s0 + tid] = 0.f;
        c_ring[s0 + tid] = 0.f;
        h2r[s0 + tid] = __float2half(0.f);
    }

    // zero masked feats rows
    for (int i = tid; i < (Ss - sl) * Hh; i += NTHR) {
        int row = sl + (i >> 7), col = i & 127;
        g_feats[((size_t)b * Ss + row) * (2 * Hh) + dir * Hh + col] = 0.f;
    }

    if (tid < Nn) {
        int bg = word_begin[b * Nn + tid];
        int ln = word_len[b * Nn + tid];
        int ef = min(bg + ln, Ss - 1);
        bool valid = ef < sl;
        if (dir == 0) {
            w_beg[tid] = bg;
            w_end[tid] = valid ? ef : -1;
        } else {
            w_beg[tid] = Ss - 1 - ef;
            w_end[tid] = valid ? (Ss - 1 - bg) : -1;
        }
    }
    __syncthreads();

    if (tid == 0) {
        for (int t = 0; t < Ss; t++) cur[t] = 0;
        for (int n = 0; n < Nn; n++) { int e = w_end[n]; if (e >= 0) cur[e]++; }
        el_start[0] = 0;
        for (int t = 0; t < Ss; t++) el_start[t + 1] = el_start[t] + cur[t];
        for (int t = 0; t < Ss; t++) cur[t] = el_start[t];
        for (int n = 0; n < Nn; n++) { int e = w_end[n]; if (e >= 0) el_idx[cur[e]++] = n; }
        *step_flag = t0;
        *words_done = 0;
    }
    __syncthreads();

    if (tid >= 512) {
        // ================= free-running word pipeline =================
        int wt = tid - 512;
        const uint4* ww = (const uint4*)wwh_h;
        const uint4* wl = (const uint4*)(g_Wlc16 + (size_t)dir * 128 * 128);
        int total = el_start[Ss];
        for (int wv = 0; wv < total; wv++) {
            int n  = el_idx[wv];
            int bg = w_beg[n];
            int e  = w_end[n];
            if (*step_flag < bg) {
                do { __nanosleep(64); } while (*step_flag < bg);
            }
            __threadfence_block();
            int bgS = (bg & 7) * Hh;
            const float4* hb4 = (const float4*)(h_ring + bgS);
            float acc0 = __ldg(Wg_b + (size_t)n * 384 + wt);
            float acc1 = __ldg(Wg_b + (size_t)n * 384 + wt + 128);
            float acc2 = __ldg(Wg_b + (size_t)n * 384 + wt + 256);
#pragma unroll 4
            for (int j8 = 0; j8 < 16; j8++) {
                float4 hA = hb4[2 * j8], hB = hb4[2 * j8 + 1];
                dot8acc(acc0, hA, hB, ww[j8 * 384 + wt]);
                dot8acc(acc1, hA, hB, ww[j8 * 384 + wt + 128]);
                dot8acc(acc2, hA, hB, ww[j8 * 384 + wt + 256]);
            }
            float cwv = sigf(acc1) * c_ring[bgS + wt] + sigf(acc0) * tanhfast(acc2);
            cw_store[n * 128 + wt] = cwv;
            asm volatile("bar.sync 1, 128;" ::: "memory");
            const float4* c4 = (const float4*)(cw_store + n * 128);
            float q0 = 0.f, q1 = 0.f;
#pragma unroll 4
            for (int j8 = 0; j8 < 16; j8 += 2) {
                dot8acc(q0, c4[2 * j8],     c4[2 * j8 + 1], __ldg(wl + j8 * 128 + wt));
                dot8acc(q1, c4[2 * j8 + 2], c4[2 * j8 + 3], __ldg(wl + (j8 + 1) * 128 + wt));
            }
            float ew = __expf(sigf(__ldg(Xl_b + (size_t)e * 128 + wt) + q0 + q1));
            ew_store[n * 128 + wt] = ew;
            asm volatile("bar.sync 1, 128;" ::: "memory");
            if (wt == 0) *words_done = wv + 1;
        }
    } else {
        // ================= step-locked char + update =================
        float xg = Xg_b[(size_t)t0 * 512 + tid];
        int gt = tid >> 7;
        const __half2 hz = __floats2half2_rn(0.f, 0.f);
        const uint4* wt4 = (const uint4*)wcht;   // [q*512 + tid]

        for (int t = t0; t < t1; t++) {
            int curS = (t & 7) * Hh;
            int nxtS = ((t + 1) & 7) * Hh;

            asm volatile("bar.sync 4, 512;" ::: "memory");   // state t ready
            float xg_cur = xg;
            if (t + 1 < t1) xg = Xg_b[(size_t)(t + 1) * 512 + tid];

            const uint4* h2q = (const uint4*)(h2r + curS);
            __half2 a0 = hz, a1 = hz, a2 = hz, a3 = hz;
            // rows 0..95 from registers
#pragma unroll
            for (int q = 0; q < 12; q++) {
                uint4 hv = h2q[q];
                a0 = __hfma2(u2h2(hv.x), wh[4 * q + 0], a0);
                a1 = __hfma2(u2h2(hv.y), wh[4 * q + 1], a1);
                a2 = __hfma2(u2h2(hv.z), wh[4 * q + 2], a2);
                a3 = __hfma2(u2h2(hv.w), wh[4 * q + 3], a3);
            }
            // rows 96..127 from smem quad bank
#pragma unroll
            for (int q = 0; q < 4; q++) {
                uint4 hv = h2q[12 + q];
                uint4 wq = wt4[q * 512 + tid];
                a0 = __hfma2(u2h2(hv.x), u2h2(wq.x), a0);
                a1 = __hfma2(u2h2(hv.y), u2h2(wq.y), a1);
                a2 = __hfma2(u2h2(hv.z), u2h2(wq.z), a2);
                a3 = __hfma2(u2h2(hv.w), u2h2(wq.w), a3);
            }
            float2 f0 = __half22float2(a0);
            float2 f1 = __half22float2(a1);
            float2 f2 = __half22float2(a2);
            float2 f3 = __half22float2(a3);
            float gv = xg_cur + ((f0.x + f0.y) + (f1.x + f1.y))
                              + ((f2.x + f2.y) + (f3.x + f3.y));
            gates[tid] = (gt == 3) ? tanhfast(gv) : sigf(gv);
            asm volatile("bar.sync 4, 512;" ::: "memory");   // gates ready

            if (tid < 128) {
                int wls = el_start[t];
                int m = el_start[t + 1] - wls;
                float ig = gates[tid];
                float fg = gates[Hh + tid];
                float og = gates[2 * Hh + tid];
                float gg = gates[3 * Hh + tid];
                float cp = c_ring[curS + tid];
                float ct;
                if (m > 0) {
                    int target = wls + m;
                    if (*words_done < target) {
                        do { __nanosleep(32); } while (*words_done < target);
                    }
                    __threadfence_block();
                    float sew = 0.f, sewc = 0.f;
                    for (int wv = 0; wv < m; wv++) {
                        int n = el_idx[wls + wv];
                        float ew = ew_store[n * 128 + tid];
                        sew  += ew;
                        sewc += ew * cw_store[n * 128 + tid];
                    }
                    float ec = __expf(ig);
                    ct = __fdividef(ec * gg + sewc, ec + sew);
                } else {
                    ct = fg * cp + ig * gg;
                }
                float ht = og * tanhfast(ct);
                h_ring[nxtS + tid] = ht;
                c_ring[nxtS + tid] = ct;
                h2r[nxtS + tid] = __float2half(ht);
                int tt = (dir == 0) ? t : (Ss - 1 - t);
                g_feats[((size_t)b * Ss + tt) * (2 * Hh) + dir * Hh + tid] = ht;
                asm volatile("bar.sync 5, 128;" ::: "memory");
                if (tid == 0) *step_flag = t + 1;
            }
        }
    }
}

// ---------------------------------------------------------------------------
// Dense projection
// ---------------------------------------------------------------------------
__global__ void dense_kernel(const float* __restrict__ W, const float* __restrict__ bias)
{
    __shared__ float fs[8][2 * Hh];
    int row0 = blockIdx.x * 8;
    int tid = threadIdx.x;
    for (int idx = tid; idx < 8 * 2 * Hh; idx += 256) {
        int r = idx >> 8;
        int e = idx & 255;
        fs[r][e] = g_feats[(size_t)(row0 + r) * (2 * Hh) + e];
    }
    __syncthreads();
    int r = tid >> 5;
    int col = tid & 31;
    float acc = bias[col];
#pragma unroll 8
    for (int e = 0; e < 2 * Hh; e++) acc = fmaf(fs[r][e], W[e * Ll + col], acc);
    g_logits[(size_t)(row0 + r) * Ll + col] = acc;
}

// ---------------------------------------------------------------------------
// CRF
// ---------------------------------------------------------------------------
__global__ void crf_kernel(const int* __restrict__ label,
                           const int* __restrict__ seqlen,
                           const float* __restrict__ T)
{
    int b = blockIdx.x;
    int j = threadIdx.x;
    int sl = seqlen[b];
    const float* lg = g_logits + (size_t)b * Ss * Ll;
    const int*   lab = label + b * Ss;

    float Tc[32];
#pragma unroll
    for (int i = 0; i < 32; i++) Tc[i] = T[i * Ll + j];

    float gold = 0.f;
    for (int t = j; t < Ss; t += 32)
        if (t < sl) gold += lg[t * Ll + lab[t]];
    for (int t = j + 1; t < Ss; t += 32)
        if (t < sl) gold += T[lab[t - 1] * Ll + lab[t]];
#pragma unroll
    for (int o = 16; o; o >>= 1) gold += __shfl_xor_sync(0xffffffffu, gold, o);

    float alpha = lg[j];
    for (int t = 1; t < Ss; t++) {
        float vmax = -1e30f;
#pragma unroll
        for (int i = 0; i < 32; i++) {
            float ai = __shfl_sync(0xffffffffu, alpha, i);
            vmax = fmaxf(vmax, ai + Tc[i]);
        }
        float s = 0.f;
#pragma unroll
        for (int i = 0; i < 32; i++) {
            float ai = __shfl_sync(0xffffffffu, alpha, i);
            s += expf(ai + Tc[i] - vmax);
        }
        float na = vmax + logf(s) + lg[(size_t)t * Ll + j];
        if (t < sl) alpha = na;
    }
    float m2 = alpha;
#pragma unroll
    for (int o = 16; o; o >>= 1) m2 = fmaxf(m2, __shfl_xor_sync(0xffffffffu, m2, o));
    float s2 = expf(alpha - m2);
#pragma unroll
    for (int o = 16; o; o >>= 1) s2 += __shfl_xor_sync(0xffffffffu, s2, o);
    if (j == 0) g_pb[b] = (m2 + logf(s2)) - gold;
}

__global__ void finalize_kernel(float* __restrict__ out)
{
    float s = 0.f;
#pragma unroll
    for (int i = 0; i < Bb; i++) s += g_pb[i];
    out[0] = s / (float)Bb;
}

// ---------------------------------------------------------------------------
// Launch
// ---------------------------------------------------------------------------
extern "C" void kernel_launch(void* const* d_in, const int* in_sizes, int n_in,
                              void* d_out, int out_size)
{
    const int* char_ids = (const int*)d_in[0];
    const int* kb_ids   = (const int*)d_in[1];
    const int* wbeg     = (const int*)d_in[2];
    const int* wlen     = (const int*)d_in[3];
    const int* label    = (const int*)d_in[4];
    const int* slen     = (const int*)d_in[5];
    const float* char_emb = (const float*)d_in[6];
    const float* kb_emb   = (const float*)d_in[7];
    const float* dense_W  = (const float*)d_in[8];
    const float* dense_b  = (const float*)d_in[9];
    const float* crf_T    = (const float*)d_in[10];

    const float* f_Wcx = (const float*)d_in[11];
    const float* f_Wch = (const float*)d_in[12];
    const float* f_bc  = (const float*)d_in[13];
    const float* f_Wwx = (const float*)d_in[14];
    const float* f_Wwh = (const float*)d_in[15];
    const float* f_bw  = (const float*)d_in[16];
    const float* f_Wlx = (const float*)d_in[17];
    const float* f_Wlc = (const float*)d_in[18];
    const float* f_bl  = (const float*)d_in[19];

    const float* r_Wcx = (const float*)d_in[20];
    const float* r_Wch = (const float*)d_in[21];
    const float* r_bc  = (const float*)d_in[22];
    const float* r_Wwx = (const float*)d_in[23];
    const float* r_Wwh = (const float*)d_in[24];
    const float* r_bw  = (const float*)d_in[25];
    const float* r_Wlx = (const float*)d_in[26];
    const float* r_Wlc = (const float*)d_in[27];
    const float* r_bl  = (const float*)d_in[28];

    prep_pack_kernel<<<dim3(192, 4), 256>>>(f_Wwh, r_Wwh, f_Wlc, r_Wlc);

    char_gather_kernel<<<dim3(Bb, Ss / 8), 256>>>(char_emb, char_ids,
        f_Wcx, r_Wcx, f_Wlx, r_Wlx, f_bc, r_bc, f_bl, r_bl);
    kb_gather_kernel<<<dim3(Bb, Nn / 8), 256>>>(kb_emb, kb_ids,
        f_Wwx, r_Wwx, f_bw, r_bw);

    cudaFuncSetAttribute(lattice_kernel, cudaFuncAttributeMaxDynamicSharedMemorySize, SMEM_LAT);
    lattice_kernel<<<2 * Bb, NTHR, SMEM_LAT>>>(f_Wch, r_Wch, wbeg, wlen, slen);

    dense_kernel<<<(Bb * Ss) / 8, 256>>>(dense_W, dense_b);
    crf_kernel<<<Bb, 32>>>(label, slen, crf_T);
    finalize_kernel<<<1, 1>>>((float*)d_out);
}

// round 13
// speedup vs baseline: 1.2454x; 1.2454x over previous
#include <cuda_runtime.h>
#include <cuda_fp16.h>
#include <math.h>

#define Bb 16
#define Ss 128
#define Nn 64
#define Ee 128
#define Hh 128
#define Ll 32

// ---------------------------------------------------------------------------
// Device-global scratch
// ---------------------------------------------------------------------------
__device__ float g_Xg[(size_t)2 * Bb * Ss * 4 * Hh];   // (dir,b,t,512)
__device__ float g_Xl[(size_t)2 * Bb * Ss * Hh];       // (dir,b,t,128)
__device__ float g_Wg[(size_t)2 * Bb * Nn * 3 * Hh];   // (dir,b,n,384)
__device__ __half g_Wwh16[(size_t)2 * 128 * 384];      // (dir, (j8*384+k)*8+i)
__device__ __half g_Wlc16[(size_t)2 * 128 * 128];      // (dir, (j8*128+k)*8+i)
__device__ float g_feats[(size_t)Bb * Ss * 2 * Hh];
__device__ float g_logits[(size_t)Bb * Ss * Ll];
__device__ float g_pb[Bb];

// fast transcendentals (~2 ulp; tolerance is 1e-3)
__device__ __forceinline__ float sigf(float x) {
    return __fdividef(1.f, 1.f + __expf(-x));
}
__device__ __forceinline__ float tanhfast(float x) {
    return 1.f - 2.f * __fdividef(1.f, __expf(2.f * x) + 1.f);
}

__device__ __forceinline__ __half2 u2h2(unsigned int v) {
    return *reinterpret_cast<const __half2*>(&v);
}

// 4 packed HFMA2: accumulate 8 fp16 products (h quad × w quad) into acc
__device__ __forceinline__ void hdot8(__half2& acc, uint4 h, uint4 w) {
    acc = __hfma2(u2h2(h.x), u2h2(w.x), acc);
    acc = __hfma2(u2h2(h.y), u2h2(w.y), acc);
    acc = __hfma2(u2h2(h.z), u2h2(w.z), acc);
    acc = __hfma2(u2h2(h.w), u2h2(w.w), acc);
}

// ---------------------------------------------------------------------------
// Prep: pack Wwh/Wlc into fp16 8-row-quad layouts
// ---------------------------------------------------------------------------
__global__ void prep_pack_kernel(const float* __restrict__ fWwh,
                                 const float* __restrict__ rWwh,
                                 const float* __restrict__ fWlc,
                                 const float* __restrict__ rWlc)
{
    int which = blockIdx.y;
    int idx = blockIdx.x * 256 + threadIdx.x;
    if (which < 2) {
        const float* in = which ? rWwh : fWwh;
        __half* out = g_Wwh16 + (size_t)which * 128 * 384;
        if (idx < 128 * 384) {
            int j = idx / 384, k = idx - j * 384;
            out[((size_t)(j >> 3) * 384 + k) * 8 + (j & 7)] = __float2half(in[idx]);
        }
    } else {
        const float* in = (which == 3) ? rWlc : fWlc;
        __half* out = g_Wlc16 + (size_t)(which - 2) * 128 * 128;
        if (idx < 128 * 128) {
            int j = idx >> 7, k = idx & 127;
            out[((size_t)(j >> 3) * 128 + k) * 8 + (j & 7)] = __float2half(in[idx]);
        }
    }
}

// ---------------------------------------------------------------------------
// Fused char-side gather GEMM
// ---------------------------------------------------------------------------
__global__ void __launch_bounds__(256) char_gather_kernel(
    const float* __restrict__ emb, const int* __restrict__ ids,
    const float* __restrict__ fWcx, const float* __restrict__ rWcx,
    const float* __restrict__ fWlx, const float* __restrict__ rWlx,
    const float* __restrict__ fbc, const float* __restrict__ rbc,
    const float* __restrict__ fbl, const float* __restrict__ rbl)
{
    __shared__ float xs[8][128];
    int b = blockIdx.x, r0 = blockIdx.y * 8, tid = threadIdx.x;

    for (int idx = tid; idx < 8 * 128; idx += 256) {
        int r = idx >> 7, e = idx & 127;
        int id = ids[b * Ss + r0 + r];
        xs[r][e] = emb[(size_t)id * 128 + e];
    }
    __syncthreads();

    const float* wp[5];
    float bias[5];
    float* op[5];
    int ostep[5];

    wp[0] = fWcx + tid;        bias[0] = fbc[tid];
    wp[1] = fWcx + tid + 256;  bias[1] = fbc[tid + 256];
    op[0] = g_Xg + ((size_t)b * Ss + r0) * 512 + tid;
    op[1] = op[0] + 256;
    ostep[0] = ostep[1] = 512;
    wp[2] = rWcx + tid;        bias[2] = rbc[tid];
    wp[3] = rWcx + tid + 256;  bias[3] = rbc[tid + 256];
    op[2] = g_Xg + ((size_t)(Bb + b) * Ss + (Ss - 1 - r0)) * 512 + tid;
    op[3] = op[2] + 256;
    ostep[2] = ostep[3] = -512;
    if (tid < 128) {
        wp[4] = fWlx + tid; bias[4] = fbl[tid];
        op[4] = g_Xl + ((size_t)b * Ss + r0) * 128 + tid;
        ostep[4] = 128;
    } else {
        int c = tid - 128;
        wp[4] = rWlx + c; bias[4] = rbl[c];
        op[4] = g_Xl + ((size_t)(Bb + b) * Ss + (Ss - 1 - r0)) * 128 + c;
        ostep[4] = -128;
    }

    float acc[8][5];
#pragma unroll
    for (int r = 0; r < 8; r++)
#pragma unroll
        for (int s = 0; s < 5; s++) acc[r][s] = 0.f;

    for (int e = 0; e < 128; e++) {
        float w0 = wp[0][(size_t)e * 512];
        float w1 = wp[1][(size_t)e * 512];
        float w2 = wp[2][(size_t)e * 512];
        float w3 = wp[3][(size_t)e * 512];
        float w4 = wp[4][(size_t)e * 128];
#pragma unroll
        for (int r = 0; r < 8; r++) {
            float x = xs[r][e];
            acc[r][0] = fmaf(x, w0, acc[r][0]);
            acc[r][1] = fmaf(x, w1, acc[r][1]);
            acc[r][2] = fmaf(x, w2, acc[r][2]);
            acc[r][3] = fmaf(x, w3, acc[r][3]);
            acc[r][4] = fmaf(x, w4, acc[r][4]);
        }
    }

#pragma unroll
    for (int r = 0; r < 8; r++)
#pragma unroll
        for (int s = 0; s < 5; s++)
            op[s][(long)r * ostep[s]] = acc[r][s] + bias[s];
}

// ---------------------------------------------------------------------------
// Fused kb-side gather GEMM
// ---------------------------------------------------------------------------
__global__ void __launch_bounds__(256) kb_gather_kernel(
    const float* __restrict__ emb, const int* __restrict__ ids,
    const float* __restrict__ fW, const float* __restrict__ rW,
    const float* __restrict__ fb, const float* __restrict__ rb)
{
    __shared__ float xs[8][128];
    int b = blockIdx.x, r0 = blockIdx.y * 8, tid = threadIdx.x;

    for (int idx = tid; idx < 8 * 128; idx += 256) {
        int r = idx >> 7, e = idx & 127;
        int id = ids[b * Nn + r0 + r];
        xs[r][e] = emb[(size_t)id * 128 + e];
    }
    __syncthreads();

    const float* wp[3];
    float bias[3];
    float* op[3];
#pragma unroll
    for (int s = 0; s < 3; s++) {
        int c = tid + 256 * s;
        if (c < 384) {
            wp[s] = fW + c; bias[s] = fb[c];
            op[s] = g_Wg + ((size_t)b * Nn + r0) * 384 + c;
        } else {
            int c2 = c - 384;
            wp[s] = rW + c2; bias[s] = rb[c2];
            op[s] = g_Wg + ((size_t)(Bb + b) * Nn + r0) * 384 + c2;
        }
    }

    float acc[8][3];
#pragma unroll
    for (int r = 0; r < 8; r++)
#pragma unroll
        for (int s = 0; s < 3; s++) acc[r][s] = 0.f;

    for (int e = 0; e < 128; e++) {
        float w0 = wp[0][(size_t)e * 384];
        float w1 = wp[1][(size_t)e * 384];
        float w2 = wp[2][(size_t)e * 384];
#pragma unroll
        for (int r = 0; r < 8; r++) {
            float x = xs[r][e];
            acc[r][0] = fmaf(x, w0, acc[r][0]);
            acc[r][1] = fmaf(x, w1, acc[r][1]);
            acc[r][2] = fmaf(x, w2, acc[r][2]);
        }
    }

#pragma unroll
    for (int r = 0; r < 8; r++)
#pragma unroll
        for (int s = 0; s < 3; s++)
            op[s][(size_t)r * 384] = acc[r][s] + bias[s];
}

// ---------------------------------------------------------------------------
// Lattice LSTM (R11 structure; word path rewritten in pure HFMA2).
//   threads 0-511  : HFMA2 char matvec (Wch fp16 in regs, h as half2 ring);
//                    tid<128 also do the cell update.
//   threads 512-639: free-running word pipeline (all-HFMA2, zero converts
//                    in the hot loops; cw kept in both fp32 and fp16).
// ---------------------------------------------------------------------------
#define NTHR 640

// smem BYTE offsets (all 16B aligned)
#define OFF_WWH   0                    // 98304
#define OFF_WLC   98304                // 32768
#define OFF_H32   131072               // 8*128 f32 = 4096
#define OFF_C32   135168               // 4096
#define OFF_H2    139264               // 8*128 fp16 = 2048
#define OFF_G     141312               // 512 f32 = 2048
#define OFF_CWS   143360               // 64*128 f32 = 32768
#define OFF_EWS   176128               // 32768
#define OFF_CW2   208896               // 64*128 fp16 = 16384
#define OFF_INT   225280               // 451 ints = 1804
#define SMEM_LAT  227084

__global__ void __launch_bounds__(NTHR, 1) lattice_kernel(
    const float* __restrict__ Wch_f, const float* __restrict__ Wch_r,
    const int* __restrict__ word_begin, const int* __restrict__ word_len,
    const int* __restrict__ seqlen)
{
    extern __shared__ char smraw[];
    __half* wwh_h   = (__half*)(smraw + OFF_WWH);
    __half* wlc_h   = (__half*)(smraw + OFF_WLC);
    float* h_ring   = (float*)(smraw + OFF_H32);
    float* c_ring   = (float*)(smraw + OFF_C32);
    __half* h2r     = (__half*)(smraw + OFF_H2);
    float* gates    = (float*)(smraw + OFF_G);
    float* cw_store = (float*)(smraw + OFF_CWS);
    float* ew_store = (float*)(smraw + OFF_EWS);
    __half* cw2_st  = (__half*)(smraw + OFF_CW2);
    int* ip        = (int*)(smraw + OFF_INT);
    int* w_beg     = ip;            // 64
    int* w_end     = ip + 64;       // 64
    int* el_start  = ip + 128;      // 129
    int* el_idx    = ip + 257;      // 64
    int* cur       = ip + 321;      // 128
    volatile int* step_flag  = (volatile int*)(ip + 449);
    volatile int* words_done = (volatile int*)(ip + 450);

    int dirb = blockIdx.x;
    int dir  = dirb / Bb;
    int b    = dirb - dir * Bb;
    int tid  = threadIdx.x;
    int sl   = seqlen[b];

    const float* Wch  = dir ? Wch_r : Wch_f;
    const float* Xg_b = g_Xg + (size_t)dirb * Ss * 512;
    const float* Xl_b = g_Xl + (size_t)dirb * Ss * 128;
    const float* Wg_b = g_Wg + (size_t)dirb * Nn * 384;

    // copy prepacked Wwh/Wlc fp16 into smem
    {
        const uint4* src = (const uint4*)(g_Wwh16 + (size_t)dir * 128 * 384);
        uint4* dst = (uint4*)wwh_h;
        for (int i = tid; i < 128 * 384 / 8; i += NTHR) dst[i] = src[i];
        const uint4* src2 = (const uint4*)(g_Wlc16 + (size_t)dir * 128 * 128);
        uint4* dst2 = (uint4*)wlc_h;
        for (int i = tid; i < 128 * 128 / 8; i += NTHR) dst2[i] = src2[i];
    }

    // ALL 128 Wch rows for column tid -> 64 half2 regs (char threads)
    __half2 wh[64];
    if (tid < 512) {
#pragma unroll
        for (int j = 0; j < 64; j++)
            wh[j] = __floats2half2_rn(Wch[(size_t)(2 * j) * 512 + tid],
                                      Wch[(size_t)(2 * j + 1) * 512 + tid]);
    }

    int t0 = dir ? (Ss - sl) : 0;
    int t1 = dir ? Ss : sl;

    if (tid < 128) {
        int s0 = (t0 & 7) * Hh;
        h_ring[s0 + tid] = 0.f;
        c_ring[s0 + tid] = 0.f;
        h2r[s0 + tid] = __float2half(0.f);
    }

    // zero masked feats rows
    for (int i = tid; i < (Ss - sl) * Hh; i += NTHR) {
        int row = sl + (i >> 7), col = i & 127;
        g_feats[((size_t)b * Ss + row) * (2 * Hh) + dir * Hh + col] = 0.f;
    }

    if (tid < Nn) {
        int bg = word_begin[b * Nn + tid];
        int ln = word_len[b * Nn + tid];
        int ef = min(bg + ln, Ss - 1);
        bool valid = ef < sl;
        if (dir == 0) {
            w_beg[tid] = bg;
            w_end[tid] = valid ? ef : -1;
        } else {
            w_beg[tid] = Ss - 1 - ef;
            w_end[tid] = valid ? (Ss - 1 - bg) : -1;
        }
    }
    __syncthreads();

    if (tid == 0) {
        for (int t = 0; t < Ss; t++) cur[t] = 0;
        for (int n = 0; n < Nn; n++) { int e = w_end[n]; if (e >= 0) cur[e]++; }
        el_start[0] = 0;
        for (int t = 0; t < Ss; t++) el_start[t + 1] = el_start[t] + cur[t];
        for (int t = 0; t < Ss; t++) cur[t] = el_start[t];
        for (int n = 0; n < Nn; n++) { int e = w_end[n]; if (e >= 0) el_idx[cur[e]++] = n; }
        *step_flag = t0;
        *words_done = 0;
    }
    __syncthreads();

    if (tid >= 512) {
        // ============ free-running word pipeline (all-HFMA2) ============
        int wt = tid - 512;
        const uint4* ww = (const uint4*)wwh_h;   // [(j8*384 + col)]: rows 8j8..8j8+7
        const uint4* wl = (const uint4*)wlc_h;   // [(j8*128 + col)]
        const __half2 hz = __floats2half2_rn(0.f, 0.f);
        int total = el_start[Ss];
        for (int wv = 0; wv < total; wv++) {
            int n  = el_idx[wv];
            int bg = w_beg[n];
            int e  = w_end[n];
            if (*step_flag < bg) {
                do { __nanosleep(64); } while (*step_flag < bg);
            }
            __threadfence_block();
            int bgS = (bg & 7) * Hh;
            const uint4* hq = (const uint4*)(h2r + bgS);   // 16 quads of 8 h's
            __half2 A[12];
#pragma unroll
            for (int i = 0; i < 12; i++) A[i] = hz;
#pragma unroll
            for (int j8 = 0; j8 < 16; j8++) {
                uint4 hv = hq[j8];
                int s = j8 & 3;
                hdot8(A[s],     hv, ww[j8 * 384 + wt]);
                hdot8(A[4 + s], hv, ww[j8 * 384 + wt + 128]);
                hdot8(A[8 + s], hv, ww[j8 * 384 + wt + 256]);
            }
            float acc0 = __ldg(Wg_b + (size_t)n * 384 + wt);
            float acc1 = __ldg(Wg_b + (size_t)n * 384 + wt + 128);
            float acc2 = __ldg(Wg_b + (size_t)n * 384 + wt + 256);
#pragma unroll
            for (int i = 0; i < 4; i++) {
                float2 v0 = __half22float2(A[i]);
                float2 v1 = __half22float2(A[4 + i]);
                float2 v2 = __half22float2(A[8 + i]);
                acc0 += v0.x + v0.y;
                acc1 += v1.x + v1.y;
                acc2 += v2.x + v2.y;
            }
            float cwv = sigf(acc1) * c_ring[bgS + wt] + sigf(acc0) * tanhfast(acc2);
            cw_store[n * 128 + wt] = cwv;
            cw2_st[n * 128 + wt] = __float2half(cwv);
            asm volatile("bar.sync 1, 128;" ::: "memory");   // cw vectors complete
            const uint4* c2 = (const uint4*)(cw2_st + n * 128);
            __half2 Q0 = hz, Q1 = hz, Q2 = hz, Q3 = hz;
#pragma unroll
            for (int j8 = 0; j8 < 16; j8 += 4) {
                hdot8(Q0, c2[j8],     wl[j8 * 128 + wt]);
                hdot8(Q1, c2[j8 + 1], wl[(j8 + 1) * 128 + wt]);
                hdot8(Q2, c2[j8 + 2], wl[(j8 + 2) * 128 + wt]);
                hdot8(Q3, c2[j8 + 3], wl[(j8 + 3) * 128 + wt]);
            }
            float2 q0 = __half22float2(Q0);
            float2 q1 = __half22float2(Q1);
            float2 q2 = __half22float2(Q2);
            float2 q3 = __half22float2(Q3);
            float qsum = (q0.x + q0.y) + (q1.x + q1.y) + (q2.x + q2.y) + (q3.x + q3.y);
            float ew = __expf(sigf(__ldg(Xl_b + (size_t)e * 128 + wt) + qsum));
            ew_store[n * 128 + wt] = ew;
            asm volatile("bar.sync 1, 128;" ::: "memory");   // stores complete
            if (wt == 0) *words_done = wv + 1;
        }
    } else {
        // ================= step-locked char + update =================
        float xg = Xg_b[(size_t)t0 * 512 + tid];
        int gt = tid >> 7;
        const __half2 hz = __floats2half2_rn(0.f, 0.f);

        for (int t = t0; t < t1; t++) {
            int curS = (t & 7) * Hh;
            int nxtS = ((t + 1) & 7) * Hh;

            asm volatile("bar.sync 4, 512;" ::: "memory");   // state t ready
            float xg_cur = xg;
            if (t + 1 < t1) xg = Xg_b[(size_t)(t + 1) * 512 + tid];

            const uint4* h2q = (const uint4*)(h2r + curS);
            __half2 a0 = hz, a1 = hz, a2 = hz, a3 = hz;
#pragma unroll
            for (int q = 0; q < 16; q++) {
                uint4 hv = h2q[q];
                a0 = __hfma2(u2h2(hv.x), wh[4 * q + 0], a0);
                a1 = __hfma2(u2h2(hv.y), wh[4 * q + 1], a1);
                a2 = __hfma2(u2h2(hv.z), wh[4 * q + 2], a2);
                a3 = __hfma2(u2h2(hv.w), wh[4 * q + 3], a3);
            }
            float2 f0 = __half22float2(a0);
            float2 f1 = __half22float2(a1);
            float2 f2 = __half22float2(a2);
            float2 f3 = __half22float2(a3);
            float gv = xg_cur + ((f0.x + f0.y) + (f1.x + f1.y))
                              + ((f2.x + f2.y) + (f3.x + f3.y));
            gates[tid] = (gt == 3) ? tanhfast(gv) : sigf(gv);
            asm volatile("bar.sync 4, 512;" ::: "memory");   // gates ready

            if (tid < 128) {
                int wls = el_start[t];
                int m = el_start[t + 1] - wls;
                float ig = gates[tid];
                float fg = gates[Hh + tid];
                float og = gates[2 * Hh + tid];
                float gg = gates[3 * Hh + tid];
                float cp = c_ring[curS + tid];
                float ct;
                if (m > 0) {
                    int target = wls + m;
                    if (*words_done < target) {
                        do { __nanosleep(32); } while (*words_done < target);
                    }
                    __threadfence_block();
                    float sew = 0.f, sewc = 0.f;
                    for (int wv = 0; wv < m; wv++) {
                        int n = el_idx[wls + wv];
                        float ew = ew_store[n * 128 + tid];
                        sew  += ew;
                        sewc += ew * cw_store[n * 128 + tid];
                    }
                    float ec = __expf(ig);
                    ct = __fdividef(ec * gg + sewc, ec + sew);
                } else {
                    ct = fg * cp + ig * gg;
                }
                float ht = og * tanhfast(ct);
                h_ring[nxtS + tid] = ht;
                c_ring[nxtS + tid] = ct;
                h2r[nxtS + tid] = __float2half(ht);
                int tt = (dir == 0) ? t : (Ss - 1 - t);
                g_feats[((size_t)b * Ss + tt) * (2 * Hh) + dir * Hh + tid] = ht;
                asm volatile("bar.sync 5, 128;" ::: "memory");
                if (tid == 0) *step_flag = t + 1;
            }
        }
    }
}

// ---------------------------------------------------------------------------
// Dense projection
// ---------------------------------------------------------------------------
__global__ void dense_kernel(const float* __restrict__ W, const float* __restrict__ bias)
{
    __shared__ float fs[8][2 * Hh];
    int row0 = blockIdx.x * 8;
    int tid = threadIdx.x;
    for (int idx = tid; idx < 8 * 2 * Hh; idx += 256) {
        int r = idx >> 8;
        int e = idx & 255;
        fs[r][e] = g_feats[(size_t)(row0 + r) * (2 * Hh) + e];
    }
    __syncthreads();
    int r = tid >> 5;
    int col = tid & 31;
    float acc = bias[col];
#pragma unroll 8
    for (int e = 0; e < 2 * Hh; e++) acc = fmaf(fs[r][e], W[e * Ll + col], acc);
    g_logits[(size_t)(row0 + r) * Ll + col] = acc;
}

// ---------------------------------------------------------------------------
// CRF
// ---------------------------------------------------------------------------
__global__ void crf_kernel(const int* __restrict__ label,
                           const int* __restrict__ seqlen,
                           const float* __restrict__ T)
{
    int b = blockIdx.x;
    int j = threadIdx.x;
    int sl = seqlen[b];
    const float* lg = g_logits + (size_t)b * Ss * Ll;
    const int*   lab = label + b * Ss;

    float Tc[32];
#pragma unroll
    for (int i = 0; i < 32; i++) Tc[i] = T[i * Ll + j];

    float gold = 0.f;
    for (int t = j; t < Ss; t += 32)
        if (t < sl) gold += lg[t * Ll + lab[t]];
    for (int t = j + 1; t < Ss; t += 32)
        if (t < sl) gold += T[lab[t - 1] * Ll + lab[t]];
#pragma unroll
    for (int o = 16; o; o >>= 1) gold += __shfl_xor_sync(0xffffffffu, gold, o);

    float alpha = lg[j];
    for (int t = 1; t < Ss; t++) {
        float vmax = -1e30f;
#pragma unroll
        for (int i = 0; i < 32; i++) {
            float ai = __shfl_sync(0xffffffffu, alpha, i);
            vmax = fmaxf(vmax, ai + Tc[i]);
        }
        float s = 0.f;
#pragma unroll
        for (int i = 0; i < 32; i++) {
            float ai = __shfl_sync(0xffffffffu, alpha, i);
            s += expf(ai + Tc[i] - vmax);
        }
        float na = vmax + logf(s) + lg[(size_t)t * Ll + j];
        if (t < sl) alpha = na;
    }
    float m2 = alpha;
#pragma unroll
    for (int o = 16; o; o >>= 1) m2 = fmaxf(m2, __shfl_xor_sync(0xffffffffu, m2, o));
    float s2 = expf(alpha - m2);
#pragma unroll
    for (int o = 16; o; o >>= 1) s2 += __shfl_xor_sync(0xffffffffu, s2, o);
    if (j == 0) g_pb[b] = (m2 + logf(s2)) - gold;
}

__global__ void finalize_kernel(float* __restrict__ out)
{
    float s = 0.f;
#pragma unroll
    for (int i = 0; i < Bb; i++) s += g_pb[i];
    out[0] = s / (float)Bb;
}

// ---------------------------------------------------------------------------
// Launch
// ---------------------------------------------------------------------------
extern "C" void kernel_launch(void* const* d_in, const int* in_sizes, int n_in,
                              void* d_out, int out_size)
{
    const int* char_ids = (const int*)d_in[0];
    const int* kb_ids   = (const int*)d_in[1];
    const int* wbeg     = (const int*)d_in[2];
    const int* wlen     = (const int*)d_in[3];
    const int* label    = (const int*)d_in[4];
    const int* slen     = (const int*)d_in[5];
    const float* char_emb = (const float*)d_in[6];
    const float* kb_emb   = (const float*)d_in[7];
    const float* dense_W  = (const float*)d_in[8];
    const float* dense_b  = (const float*)d_in[9];
    const float* crf_T    = (const float*)d_in[10];

    const float* f_Wcx = (const float*)d_in[11];
    const float* f_Wch = (const float*)d_in[12];
    const float* f_bc  = (const float*)d_in[13];
    const float* f_Wwx = (const float*)d_in[14];
    const float* f_Wwh = (const float*)d_in[15];
    const float* f_bw  = (const float*)d_in[16];
    const float* f_Wlx = (const float*)d_in[17];
    const float* f_Wlc = (const float*)d_in[18];
    const float* f_bl  = (const float*)d_in[19];

    const float* r_Wcx = (const float*)d_in[20];
    const float* r_Wch = (const float*)d_in[21];
    const float* r_bc  = (const float*)d_in[22];
    const float* r_Wwx = (const float*)d_in[23];
    const float* r_Wwh = (const float*)d_in[24];
    const float* r_bw  = (const float*)d_in[25];
    const float* r_Wlx = (const float*)d_in[26];
    const float* r_Wlc = (const float*)d_in[27];
    const float* r_bl  = (const float*)d_in[28];

    prep_pack_kernel<<<dim3(192, 4), 256>>>(f_Wwh, r_Wwh, f_Wlc, r_Wlc);

    char_gather_kernel<<<dim3(Bb, Ss / 8), 256>>>(char_emb, char_ids,
        f_Wcx, r_Wcx, f_Wlx, r_Wlx, f_bc, r_bc, f_bl, r_bl);
    kb_gather_kernel<<<dim3(Bb, Nn / 8), 256>>>(kb_emb, kb_ids,
        f_Wwx, r_Wwx, f_bw, r_bw);

    cudaFuncSetAttribute(lattice_kernel, cudaFuncAttributeMaxDynamicSharedMemorySize, SMEM_LAT);
    lattice_kernel<<<2 * Bb, NTHR, SMEM_LAT>>>(f_Wch, r_Wch, wbeg, wlen, slen);

    dense_kernel<<<(Bb * Ss) / 8, 256>>>(dense_W, dense_b);
    crf_kernel<<<Bb, 32>>>(label, slen, crf_T);
    finalize_kernel<<<1, 1>>>((float*)d_out);
}

// round 14
// speedup vs baseline: 1.2657x; 1.0163x over previous
#include <cuda_runtime.h>
#include <cuda_fp16.h>
#include <math.h>

#define Bb 16
#define Ss 128
#define Nn 64
#define Ee 128
#define Hh 128
#define Ll 32

// ---------------------------------------------------------------------------
// Device-global scratch
// ---------------------------------------------------------------------------
__device__ float g_Xg[(size_t)2 * Bb * Ss * 4 * Hh];   // (dir,b,t,512)
__device__ float g_Xl[(size_t)2 * Bb * Ss * Hh];       // (dir,b,t,128)
__device__ float g_Wg[(size_t)2 * Bb * Nn * 3 * Hh];   // (dir,b,n,384)
__device__ __half g_Wwh16[(size_t)2 * 128 * 384];      // (dir, (j8*384+k)*8+i)
__device__ __half g_Wlc16[(size_t)2 * 128 * 128];      // (dir, (j8*128+k)*8+i)
__device__ float g_feats[(size_t)Bb * Ss * 2 * Hh];
__device__ float g_logits[(size_t)Bb * Ss * Ll];
__device__ float g_pb[Bb];

// fast transcendentals (~2 ulp; tolerance is 1e-3)
__device__ __forceinline__ float sigf(float x) {
    return __fdividef(1.f, 1.f + __expf(-x));
}
__device__ __forceinline__ float tanhfast(float x) {
    return 1.f - 2.f * __fdividef(1.f, __expf(2.f * x) + 1.f);
}

__device__ __forceinline__ __half2 u2h2(unsigned int v) {
    return *reinterpret_cast<const __half2*>(&v);
}

// 4 packed HFMA2: accumulate 8 fp16 products (h quad × w quad) into acc
__device__ __forceinline__ void hdot8(__half2& acc, uint4 h, uint4 w) {
    acc = __hfma2(u2h2(h.x), u2h2(w.x), acc);
    acc = __hfma2(u2h2(h.y), u2h2(w.y), acc);
    acc = __hfma2(u2h2(h.z), u2h2(w.z), acc);
    acc = __hfma2(u2h2(h.w), u2h2(w.w), acc);
}

// ---------------------------------------------------------------------------
// Prep: pack Wwh/Wlc into fp16 8-row-quad layouts
// ---------------------------------------------------------------------------
__global__ void prep_pack_kernel(const float* __restrict__ fWwh,
                                 const float* __restrict__ rWwh,
                                 const float* __restrict__ fWlc,
                                 const float* __restrict__ rWlc)
{
    int which = blockIdx.y;
    int idx = blockIdx.x * 256 + threadIdx.x;
    if (which < 2) {
        const float* in = which ? rWwh : fWwh;
        __half* out = g_Wwh16 + (size_t)which * 128 * 384;
        if (idx < 128 * 384) {
            int j = idx / 384, k = idx - j * 384;
            out[((size_t)(j >> 3) * 384 + k) * 8 + (j & 7)] = __float2half(in[idx]);
        }
    } else {
        const float* in = (which == 3) ? rWlc : fWlc;
        __half* out = g_Wlc16 + (size_t)(which - 2) * 128 * 128;
        if (idx < 128 * 128) {
            int j = idx >> 7, k = idx & 127;
            out[((size_t)(j >> 3) * 128 + k) * 8 + (j & 7)] = __float2half(in[idx]);
        }
    }
}

// ---------------------------------------------------------------------------
// Fused char-side gather GEMM — 16 rows per CTA (halves L2 weight traffic)
// ---------------------------------------------------------------------------
__global__ void __launch_bounds__(256) char_gather_kernel(
    const float* __restrict__ emb, const int* __restrict__ ids,
    const float* __restrict__ fWcx, const float* __restrict__ rWcx,
    const float* __restrict__ fWlx, const float* __restrict__ rWlx,
    const float* __restrict__ fbc, const float* __restrict__ rbc,
    const float* __restrict__ fbl, const float* __restrict__ rbl)
{
    __shared__ float xs[16][128];
    int b = blockIdx.x, r0 = blockIdx.y * 16, tid = threadIdx.x;

    for (int idx = tid; idx < 16 * 128; idx += 256) {
        int r = idx >> 7, e = idx & 127;
        int id = ids[b * Ss + r0 + r];
        xs[r][e] = emb[(size_t)id * 128 + e];
    }
    __syncthreads();

    const float* wp[5];
    float bias[5];
    float* op[5];
    int ostep[5];

    wp[0] = fWcx + tid;        bias[0] = fbc[tid];
    wp[1] = fWcx + tid + 256;  bias[1] = fbc[tid + 256];
    op[0] = g_Xg + ((size_t)b * Ss + r0) * 512 + tid;
    op[1] = op[0] + 256;
    ostep[0] = ostep[1] = 512;
    wp[2] = rWcx + tid;        bias[2] = rbc[tid];
    wp[3] = rWcx + tid + 256;  bias[3] = rbc[tid + 256];
    op[2] = g_Xg + ((size_t)(Bb + b) * Ss + (Ss - 1 - r0)) * 512 + tid;
    op[3] = op[2] + 256;
    ostep[2] = ostep[3] = -512;
    if (tid < 128) {
        wp[4] = fWlx + tid; bias[4] = fbl[tid];
        op[4] = g_Xl + ((size_t)b * Ss + r0) * 128 + tid;
        ostep[4] = 128;
    } else {
        int c = tid - 128;
        wp[4] = rWlx + c; bias[4] = rbl[c];
        op[4] = g_Xl + ((size_t)(Bb + b) * Ss + (Ss - 1 - r0)) * 128 + c;
        ostep[4] = -128;
    }

    float acc[16][5];
#pragma unroll
    for (int r = 0; r < 16; r++)
#pragma unroll
        for (int s = 0; s < 5; s++) acc[r][s] = 0.f;

    for (int e = 0; e < 128; e++) {
        float w0 = wp[0][(size_t)e * 512];
        float w1 = wp[1][(size_t)e * 512];
        float w2 = wp[2][(size_t)e * 512];
        float w3 = wp[3][(size_t)e * 512];
        float w4 = wp[4][(size_t)e * 128];
#pragma unroll
        for (int r = 0; r < 16; r++) {
            float x = xs[r][e];
            acc[r][0] = fmaf(x, w0, acc[r][0]);
            acc[r][1] = fmaf(x, w1, acc[r][1]);
            acc[r][2] = fmaf(x, w2, acc[r][2]);
            acc[r][3] = fmaf(x, w3, acc[r][3]);
            acc[r][4] = fmaf(x, w4, acc[r][4]);
        }
    }

#pragma unroll
    for (int r = 0; r < 16; r++)
#pragma unroll
        for (int s = 0; s < 5; s++)
            op[s][(long)r * ostep[s]] = acc[r][s] + bias[s];
}

// ---------------------------------------------------------------------------
// Fused kb-side gather GEMM (unchanged)
// ---------------------------------------------------------------------------
__global__ void __launch_bounds__(256) kb_gather_kernel(
    const float* __restrict__ emb, const int* __restrict__ ids,
    const float* __restrict__ fW, const float* __restrict__ rW,
    const float* __restrict__ fb, const float* __restrict__ rb)
{
    __shared__ float xs[8][128];
    int b = blockIdx.x, r0 = blockIdx.y * 8, tid = threadIdx.x;

    for (int idx = tid; idx < 8 * 128; idx += 256) {
        int r = idx >> 7, e = idx & 127;
        int id = ids[b * Nn + r0 + r];
        xs[r][e] = emb[(size_t)id * 128 + e];
    }
    __syncthreads();

    const float* wp[3];
    float bias[3];
    float* op[3];
#pragma unroll
    for (int s = 0; s < 3; s++) {
        int c = tid + 256 * s;
        if (c < 384) {
            wp[s] = fW + c; bias[s] = fb[c];
            op[s] = g_Wg + ((size_t)b * Nn + r0) * 384 + c;
        } else {
            int c2 = c - 384;
            wp[s] = rW + c2; bias[s] = rb[c2];
            op[s] = g_Wg + ((size_t)(Bb + b) * Nn + r0) * 384 + c2;
        }
    }

    float acc[8][3];
#pragma unroll
    for (int r = 0; r < 8; r++)
#pragma unroll
        for (int s = 0; s < 3; s++) acc[r][s] = 0.f;

    for (int e = 0; e < 128; e++) {
        float w0 = wp[0][(size_t)e * 384];
        float w1 = wp[1][(size_t)e * 384];
        float w2 = wp[2][(size_t)e * 384];
#pragma unroll
        for (int r = 0; r < 8; r++) {
            float x = xs[r][e];
            acc[r][0] = fmaf(x, w0, acc[r][0]);
            acc[r][1] = fmaf(x, w1, acc[r][1]);
            acc[r][2] = fmaf(x, w2, acc[r][2]);
        }
    }

#pragma unroll
    for (int r = 0; r < 8; r++)
#pragma unroll
        for (int s = 0; s < 3; s++)
            op[s][(size_t)r * 384] = acc[r][s] + bias[s];
}

// ---------------------------------------------------------------------------
// Lattice LSTM (unchanged from R13 — proven at 153.5us)
// ---------------------------------------------------------------------------
#define NTHR 640

// smem BYTE offsets (all 16B aligned)
#define OFF_WWH   0                    // 98304
#define OFF_WLC   98304                // 32768
#define OFF_H32   131072               // 8*128 f32 = 4096
#define OFF_C32   135168               // 4096
#define OFF_H2    139264               // 8*128 fp16 = 2048
#define OFF_G     141312               // 512 f32 = 2048
#define OFF_CWS   143360               // 64*128 f32 = 32768
#define OFF_EWS   176128               // 32768
#define OFF_CW2   208896               // 64*128 fp16 = 16384
#define OFF_INT   225280               // 451 ints = 1804
#define SMEM_LAT  227084

__global__ void __launch_bounds__(NTHR, 1) lattice_kernel(
    const float* __restrict__ Wch_f, const float* __restrict__ Wch_r,
    const int* __restrict__ word_begin, const int* __restrict__ word_len,
    const int* __restrict__ seqlen)
{
    extern __shared__ char smraw[];
    __half* wwh_h   = (__half*)(smraw + OFF_WWH);
    __half* wlc_h   = (__half*)(smraw + OFF_WLC);
    float* h_ring   = (float*)(smraw + OFF_H32);
    float* c_ring   = (float*)(smraw + OFF_C32);
    __half* h2r     = (__half*)(smraw + OFF_H2);
    float* gates    = (float*)(smraw + OFF_G);
    float* cw_store = (float*)(smraw + OFF_CWS);
    float* ew_store = (float*)(smraw + OFF_EWS);
    __half* cw2_st  = (__half*)(smraw + OFF_CW2);
    int* ip        = (int*)(smraw + OFF_INT);
    int* w_beg     = ip;            // 64
    int* w_end     = ip + 64;       // 64
    int* el_start  = ip + 128;      // 129
    int* el_idx    = ip + 257;      // 64
    int* cur       = ip + 321;      // 128
    volatile int* step_flag  = (volatile int*)(ip + 449);
    volatile int* words_done = (volatile int*)(ip + 450);

    int dirb = blockIdx.x;
    int dir  = dirb / Bb;
    int b    = dirb - dir * Bb;
    int tid  = threadIdx.x;
    int sl   = seqlen[b];

    const float* Wch  = dir ? Wch_r : Wch_f;
    const float* Xg_b = g_Xg + (size_t)dirb * Ss * 512;
    const float* Xl_b = g_Xl + (size_t)dirb * Ss * 128;
    const float* Wg_b = g_Wg + (size_t)dirb * Nn * 384;

    // copy prepacked Wwh/Wlc fp16 into smem
    {
        const uint4* src = (const uint4*)(g_Wwh16 + (size_t)dir * 128 * 384);
        uint4* dst = (uint4*)wwh_h;
        for (int i = tid; i < 128 * 384 / 8; i += NTHR) dst[i] = src[i];
        const uint4* src2 = (const uint4*)(g_Wlc16 + (size_t)dir * 128 * 128);
        uint4* dst2 = (uint4*)wlc_h;
        for (int i = tid; i < 128 * 128 / 8; i += NTHR) dst2[i] = src2[i];
    }

    // ALL 128 Wch rows for column tid -> 64 half2 regs (char threads)
    __half2 wh[64];
    if (tid < 512) {
#pragma unroll
        for (int j = 0; j < 64; j++)
            wh[j] = __floats2half2_rn(Wch[(size_t)(2 * j) * 512 + tid],
                                      Wch[(size_t)(2 * j + 1) * 512 + tid]);
    }

    int t0 = dir ? (Ss - sl) : 0;
    int t1 = dir ? Ss : sl;

    if (tid < 128) {
        int s0 = (t0 & 7) * Hh;
        h_ring[s0 + tid] = 0.f;
        c_ring[s0 + tid] = 0.f;
        h2r[s0 + tid] = __float2half(0.f);
    }

    // zero masked feats rows
    for (int i = tid; i < (Ss - sl) * Hh; i += NTHR) {
        int row = sl + (i >> 7), col = i & 127;
        g_feats[((size_t)b * Ss + row) * (2 * Hh) + dir * Hh + col] = 0.f;
    }

    if (tid < Nn) {
        int bg = word_begin[b * Nn + tid];
        int ln = word_len[b * Nn + tid];
        int ef = min(bg + ln, Ss - 1);
        bool valid = ef < sl;
        if (dir == 0) {
            w_beg[tid] = bg;
            w_end[tid] = valid ? ef : -1;
        } else {
            w_beg[tid] = Ss - 1 - ef;
            w_end[tid] = valid ? (Ss - 1 - bg) : -1;
        }
    }
    __syncthreads();

    if (tid == 0) {
        for (int t = 0; t < Ss; t++) cur[t] = 0;
        for (int n = 0; n < Nn; n++) { int e = w_end[n]; if (e >= 0) cur[e]++; }
        el_start[0] = 0;
        for (int t = 0; t < Ss; t++) el_start[t + 1] = el_start[t] + cur[t];
        for (int t = 0; t < Ss; t++) cur[t] = el_start[t];
        for (int n = 0; n < Nn; n++) { int e = w_end[n]; if (e >= 0) el_idx[cur[e]++] = n; }
        *step_flag = t0;
        *words_done = 0;
    }
    __syncthreads();

    if (tid >= 512) {
        // ============ free-running word pipeline (all-HFMA2) ============
        int wt = tid - 512;
        const uint4* ww = (const uint4*)wwh_h;
        const uint4* wl = (const uint4*)wlc_h;
        const __half2 hz = __floats2half2_rn(0.f, 0.f);
        int total = el_start[Ss];
        for (int wv = 0; wv < total; wv++) {
            int n  = el_idx[wv];
            int bg = w_beg[n];
            int e  = w_end[n];
            if (*step_flag < bg) {
                do { __nanosleep(64); } while (*step_flag < bg);
            }
            __threadfence_block();
            int bgS = (bg & 7) * Hh;
            const uint4* hq = (const uint4*)(h2r + bgS);
            __half2 A[12];
#pragma unroll
            for (int i = 0; i < 12; i++) A[i] = hz;
#pragma unroll
            for (int j8 = 0; j8 < 16; j8++) {
                uint4 hv = hq[j8];
                int s = j8 & 3;
                hdot8(A[s],     hv, ww[j8 * 384 + wt]);
                hdot8(A[4 + s], hv, ww[j8 * 384 + wt + 128]);
                hdot8(A[8 + s], hv, ww[j8 * 384 + wt + 256]);
            }
            float acc0 = __ldg(Wg_b + (size_t)n * 384 + wt);
            float acc1 = __ldg(Wg_b + (size_t)n * 384 + wt + 128);
            float acc2 = __ldg(Wg_b + (size_t)n * 384 + wt + 256);
#pragma unroll
            for (int i = 0; i < 4; i++) {
                float2 v0 = __half22float2(A[i]);
                float2 v1 = __half22float2(A[4 + i]);
                float2 v2 = __half22float2(A[8 + i]);
                acc0 += v0.x + v0.y;
                acc1 += v1.x + v1.y;
                acc2 += v2.x + v2.y;
            }
            float cwv = sigf(acc1) * c_ring[bgS + wt] + sigf(acc0) * tanhfast(acc2);
            cw_store[n * 128 + wt] = cwv;
            cw2_st[n * 128 + wt] = __float2half(cwv);
            asm volatile("bar.sync 1, 128;" ::: "memory");
            const uint4* c2 = (const uint4*)(cw2_st + n * 128);
            __half2 Q0 = hz, Q1 = hz, Q2 = hz, Q3 = hz;
#pragma unroll
            for (int j8 = 0; j8 < 16; j8 += 4) {
                hdot8(Q0, c2[j8],     wl[j8 * 128 + wt]);
                hdot8(Q1, c2[j8 + 1], wl[(j8 + 1) * 128 + wt]);
                hdot8(Q2, c2[j8 + 2], wl[(j8 + 2) * 128 + wt]);
                hdot8(Q3, c2[j8 + 3], wl[(j8 + 3) * 128 + wt]);
            }
            float2 q0 = __half22float2(Q0);
            float2 q1 = __half22float2(Q1);
            float2 q2 = __half22float2(Q2);
            float2 q3 = __half22float2(Q3);
            float qsum = (q0.x + q0.y) + (q1.x + q1.y) + (q2.x + q2.y) + (q3.x + q3.y);
            float ew = __expf(sigf(__ldg(Xl_b + (size_t)e * 128 + wt) + qsum));
            ew_store[n * 128 + wt] = ew;
            asm volatile("bar.sync 1, 128;" ::: "memory");
            if (wt == 0) *words_done = wv + 1;
        }
    } else {
        // ================= step-locked char + update =================
        float xg = Xg_b[(size_t)t0 * 512 + tid];
        int gt = tid >> 7;
        const __half2 hz = __floats2half2_rn(0.f, 0.f);

        for (int t = t0; t < t1; t++) {
            int curS = (t & 7) * Hh;
            int nxtS = ((t + 1) & 7) * Hh;

            asm volatile("bar.sync 4, 512;" ::: "memory");   // state t ready
            float xg_cur = xg;
            if (t + 1 < t1) xg = Xg_b[(size_t)(t + 1) * 512 + tid];

            const uint4* h2q = (const uint4*)(h2r + curS);
            __half2 a0 = hz, a1 = hz, a2 = hz, a3 = hz;
#pragma unroll
            for (int q = 0; q < 16; q++) {
                uint4 hv = h2q[q];
                a0 = __hfma2(u2h2(hv.x), wh[4 * q + 0], a0);
                a1 = __hfma2(u2h2(hv.y), wh[4 * q + 1], a1);
                a2 = __hfma2(u2h2(hv.z), wh[4 * q + 2], a2);
                a3 = __hfma2(u2h2(hv.w), wh[4 * q + 3], a3);
            }
            float2 f0 = __half22float2(a0);
            float2 f1 = __half22float2(a1);
            float2 f2 = __half22float2(a2);
            float2 f3 = __half22float2(a3);
            float gv = xg_cur + ((f0.x + f0.y) + (f1.x + f1.y))
                              + ((f2.x + f2.y) + (f3.x + f3.y));
            gates[tid] = (gt == 3) ? tanhfast(gv) : sigf(gv);
            asm volatile("bar.sync 4, 512;" ::: "memory");   // gates ready

            if (tid < 128) {
                int wls = el_start[t];
                int m = el_start[t + 1] - wls;
                float ig = gates[tid];
                float fg = gates[Hh + tid];
                float og = gates[2 * Hh + tid];
                float gg = gates[3 * Hh + tid];
                float cp = c_ring[curS + tid];
                float ct;
                if (m > 0) {
                    int target = wls + m;
                    if (*words_done < target) {
                        do { __nanosleep(32); } while (*words_done < target);
                    }
                    __threadfence_block();
                    float sew = 0.f, sewc = 0.f;
                    for (int wv = 0; wv < m; wv++) {
                        int n = el_idx[wls + wv];
                        float ew = ew_store[n * 128 + tid];
                        sew  += ew;
                        sewc += ew * cw_store[n * 128 + tid];
                    }
                    float ec = __expf(ig);
                    ct = __fdividef(ec * gg + sewc, ec + sew);
                } else {
                    ct = fg * cp + ig * gg;
                }
                float ht = og * tanhfast(ct);
                h_ring[nxtS + tid] = ht;
                c_ring[nxtS + tid] = ct;
                h2r[nxtS + tid] = __float2half(ht);
                int tt = (dir == 0) ? t : (Ss - 1 - t);
                g_feats[((size_t)b * Ss + tt) * (2 * Hh) + dir * Hh + tid] = ht;
                asm volatile("bar.sync 5, 128;" ::: "memory");
                if (tid == 0) *step_flag = t + 1;
            }
        }
    }
}

// ---------------------------------------------------------------------------
// Dense projection
// ---------------------------------------------------------------------------
__global__ void dense_kernel(const float* __restrict__ W, const float* __restrict__ bias)
{
    __shared__ float fs[8][2 * Hh];
    int row0 = blockIdx.x * 8;
    int tid = threadIdx.x;
    for (int idx = tid; idx < 8 * 2 * Hh; idx += 256) {
        int r = idx >> 8;
        int e = idx & 255;
        fs[r][e] = g_feats[(size_t)(row0 + r) * (2 * Hh) + e];
    }
    __syncthreads();
    int r = tid >> 5;
    int col = tid & 31;
    float acc = bias[col];
#pragma unroll 8
    for (int e = 0; e < 2 * Hh; e++) acc = fmaf(fs[r][e], W[e * Ll + col], acc);
    g_logits[(size_t)(row0 + r) * Ll + col] = acc;
}

// ---------------------------------------------------------------------------
// CRF — fast transcendentals (__expf/__logf), same structure
// ---------------------------------------------------------------------------
__global__ void crf_kernel(const int* __restrict__ label,
                           const int* __restrict__ seqlen,
                           const float* __restrict__ T)
{
    int b = blockIdx.x;
    int j = threadIdx.x;
    int sl = seqlen[b];
    const float* lg = g_logits + (size_t)b * Ss * Ll;
    const int*   lab = label + b * Ss;

    float Tc[32];
#pragma unroll
    for (int i = 0; i < 32; i++) Tc[i] = T[i * Ll + j];

    float gold = 0.f;
    for (int t = j; t < Ss; t += 32)
        if (t < sl) gold += lg[t * Ll + lab[t]];
    for (int t = j + 1; t < Ss; t += 32)
        if (t < sl) gold += T[lab[t - 1] * Ll + lab[t]];
#pragma unroll
    for (int o = 16; o; o >>= 1) gold += __shfl_xor_sync(0xffffffffu, gold, o);

    float alpha = lg[j];
    for (int t = 1; t < Ss; t++) {
        float vmax = -1e30f;
#pragma unroll
        for (int i = 0; i < 32; i++) {
            float ai = __shfl_sync(0xffffffffu, alpha, i);
            vmax = fmaxf(vmax, ai + Tc[i]);
        }
        float s = 0.f;
#pragma unroll
        for (int i = 0; i < 32; i++) {
            float ai = __shfl_sync(0xffffffffu, alpha, i);
            s += __expf(ai + Tc[i] - vmax);
        }
        float na = vmax + __logf(s) + lg[(size_t)t * Ll + j];
        if (t < sl) alpha = na;
    }
    float m2 = alpha;
#pragma unroll
    for (int o = 16; o; o >>= 1) m2 = fmaxf(m2, __shfl_xor_sync(0xffffffffu, m2, o));
    float s2 = __expf(alpha - m2);
#pragma unroll
    for (int o = 16; o; o >>= 1) s2 += __shfl_xor_sync(0xffffffffu, s2, o);
    if (j == 0) g_pb[b] = (m2 + __logf(s2)) - gold;
}

__global__ void finalize_kernel(float* __restrict__ out)
{
    float s = 0.f;
#pragma unroll
    for (int i = 0; i < Bb; i++) s += g_pb[i];
    out[0] = s / (float)Bb;
}

// ---------------------------------------------------------------------------
// Launch
// ---------------------------------------------------------------------------
extern "C" void kernel_launch(void* const* d_in, const int* in_sizes, int n_in,
                              void* d_out, int out_size)
{
    const int* char_ids = (const int*)d_in[0];
    const int* kb_ids   = (const int*)d_in[1];
    const int* wbeg     = (const int*)d_in[2];
    const int* wlen     = (const int*)d_in[3];
    const int* label    = (const int*)d_in[4];
    const int* slen     = (const int*)d_in[5];
    const float* char_emb = (const float*)d_in[6];
    const float* kb_emb   = (const float*)d_in[7];
    const float* dense_W  = (const float*)d_in[8];
    const float* dense_b  = (const float*)d_in[9];
    const float* crf_T    = (const float*)d_in[10];

    const float* f_Wcx = (const float*)d_in[11];
    const float* f_Wch = (const float*)d_in[12];
    const float* f_bc  = (const float*)d_in[13];
    const float* f_Wwx = (const float*)d_in[14];
    const float* f_Wwh = (const float*)d_in[15];
    const float* f_bw  = (const float*)d_in[16];
    const float* f_Wlx = (const float*)d_in[17];
    const float* f_Wlc = (const float*)d_in[18];
    const float* f_bl  = (const float*)d_in[19];

    const float* r_Wcx = (const float*)d_in[20];
    const float* r_Wch = (const float*)d_in[21];
    const float* r_bc  = (const float*)d_in[22];
    const float* r_Wwx = (const float*)d_in[23];
    const float* r_Wwh = (const float*)d_in[24];
    const float* r_bw  = (const float*)d_in[25];
    const float* r_Wlx = (const float*)d_in[26];
    const float* r_Wlc = (const float*)d_in[27];
    const float* r_bl  = (const float*)d_in[28];

    prep_pack_kernel<<<dim3(192, 4), 256>>>(f_Wwh, r_Wwh, f_Wlc, r_Wlc);

    char_gather_kernel<<<dim3(Bb, Ss / 16), 256>>>(char_emb, char_ids,
        f_Wcx, r_Wcx, f_Wlx, r_Wlx, f_bc, r_bc, f_bl, r_bl);
    kb_gather_kernel<<<dim3(Bb, Nn / 8), 256>>>(kb_emb, kb_ids,
        f_Wwx, r_Wwx, f_bw, r_bw);

    cudaFuncSetAttribute(lattice_kernel, cudaFuncAttributeMaxDynamicSharedMemorySize, SMEM_LAT);
    lattice_kernel<<<2 * Bb, NTHR, SMEM_LAT>>>(f_Wch, r_Wch, wbeg, wlen, slen);

    dense_kernel<<<(Bb * Ss) / 8, 256>>>(dense_W, dense_b);
    crf_kernel<<<Bb, 32>>>(label, slen, crf_T);
    finalize_kernel<<<1, 1>>>((float*)d_out);
}

// round 15
// speedup vs baseline: 1.2937x; 1.0222x over previous
#include <cuda_runtime.h>
#include <cuda_fp16.h>
#include <math.h>

#define Bb 16
#define Ss 128
#define Nn 64
#define Ee 128
#define Hh 128
#define Ll 32

// ---------------------------------------------------------------------------
// Device-global scratch
// ---------------------------------------------------------------------------
__device__ float g_Xg[(size_t)2 * Bb * Ss * 4 * Hh];   // (dir,b,t,512)
__device__ float g_Xl[(size_t)2 * Bb * Ss * Hh];       // (dir,b,t,128)
__device__ float g_Wg[(size_t)2 * Bb * Nn * 3 * Hh];   // (dir,b,n,384)
__device__ __half g_Wwh16[(size_t)2 * 128 * 384];      // (dir, (j8*384+k)*8+i)
__device__ __half g_Wlc16[(size_t)2 * 128 * 128];      // (dir, (j8*128+k)*8+i)
__device__ float g_feats[(size_t)Bb * Ss * 2 * Hh];
__device__ float g_logits[(size_t)Bb * Ss * Ll];
__device__ float g_pb[Bb];
__device__ int   g_crf_count;

// fast transcendentals (~2 ulp; tolerance is 1e-3)
__device__ __forceinline__ float sigf(float x) {
    return __fdividef(1.f, 1.f + __expf(-x));
}
__device__ __forceinline__ float tanhfast(float x) {
    return 1.f - 2.f * __fdividef(1.f, __expf(2.f * x) + 1.f);
}

__device__ __forceinline__ __half2 u2h2(unsigned int v) {
    return *reinterpret_cast<const __half2*>(&v);
}

// 4 packed HFMA2: accumulate 8 fp16 products (h quad × w quad) into acc
__device__ __forceinline__ void hdot8(__half2& acc, uint4 h, uint4 w) {
    acc = __hfma2(u2h2(h.x), u2h2(w.x), acc);
    acc = __hfma2(u2h2(h.y), u2h2(w.y), acc);
    acc = __hfma2(u2h2(h.z), u2h2(w.z), acc);
    acc = __hfma2(u2h2(h.w), u2h2(w.w), acc);
}

// ---------------------------------------------------------------------------
// Fused front kernel: char gather GEMM (128 CTAs) + kb gather GEMM (128 CTAs)
// + fp16 weight packing (512 CTAs). One launch replaces three.
// ---------------------------------------------------------------------------
__global__ void __launch_bounds__(256) front_kernel(
    const float* __restrict__ char_emb, const int* __restrict__ char_ids,
    const float* __restrict__ kb_emb,   const int* __restrict__ kb_ids,
    const float* __restrict__ fWcx, const float* __restrict__ rWcx,
    const float* __restrict__ fWlx, const float* __restrict__ rWlx,
    const float* __restrict__ fbc, const float* __restrict__ rbc,
    const float* __restrict__ fbl, const float* __restrict__ rbl,
    const float* __restrict__ fWwx, const float* __restrict__ rWwx,
    const float* __restrict__ fbw, const float* __restrict__ rbw,
    const float* __restrict__ fWwh, const float* __restrict__ rWwh,
    const float* __restrict__ fWlc, const float* __restrict__ rWlc)
{
    int bid = blockIdx.x;
    int tid = threadIdx.x;

    if (bid < 128) {
        // ---------------- char-side gather GEMM: 16 rows per CTA ----------
        __shared__ float xs[16][128];
        int b = bid >> 3, r0 = (bid & 7) * 16;

        for (int idx = tid; idx < 16 * 128; idx += 256) {
            int r = idx >> 7, e = idx & 127;
            int id = char_ids[b * Ss + r0 + r];
            xs[r][e] = char_emb[(size_t)id * 128 + e];
        }
        __syncthreads();

        const float* wp[5];
        float bias[5];
        float* op[5];
        int ostep[5];

        wp[0] = fWcx + tid;        bias[0] = fbc[tid];
        wp[1] = fWcx + tid + 256;  bias[1] = fbc[tid + 256];
        op[0] = g_Xg + ((size_t)b * Ss + r0) * 512 + tid;
        op[1] = op[0] + 256;
        ostep[0] = ostep[1] = 512;
        wp[2] = rWcx + tid;        bias[2] = rbc[tid];
        wp[3] = rWcx + tid + 256;  bias[3] = rbc[tid + 256];
        op[2] = g_Xg + ((size_t)(Bb + b) * Ss + (Ss - 1 - r0)) * 512 + tid;
        op[3] = op[2] + 256;
        ostep[2] = ostep[3] = -512;
        if (tid < 128) {
            wp[4] = fWlx + tid; bias[4] = fbl[tid];
            op[4] = g_Xl + ((size_t)b * Ss + r0) * 128 + tid;
            ostep[4] = 128;
        } else {
            int c = tid - 128;
            wp[4] = rWlx + c; bias[4] = rbl[c];
            op[4] = g_Xl + ((size_t)(Bb + b) * Ss + (Ss - 1 - r0)) * 128 + c;
            ostep[4] = -128;
        }

        float acc[16][5];
#pragma unroll
        for (int r = 0; r < 16; r++)
#pragma unroll
            for (int s = 0; s < 5; s++) acc[r][s] = 0.f;

        for (int e = 0; e < 128; e++) {
            float w0 = wp[0][(size_t)e * 512];
            float w1 = wp[1][(size_t)e * 512];
            float w2 = wp[2][(size_t)e * 512];
            float w3 = wp[3][(size_t)e * 512];
            float w4 = wp[4][(size_t)e * 128];
#pragma unroll
            for (int r = 0; r < 16; r++) {
                float x = xs[r][e];
                acc[r][0] = fmaf(x, w0, acc[r][0]);
                acc[r][1] = fmaf(x, w1, acc[r][1]);
                acc[r][2] = fmaf(x, w2, acc[r][2]);
                acc[r][3] = fmaf(x, w3, acc[r][3]);
                acc[r][4] = fmaf(x, w4, acc[r][4]);
            }
        }

#pragma unroll
        for (int r = 0; r < 16; r++)
#pragma unroll
            for (int s = 0; s < 5; s++)
                op[s][(long)r * ostep[s]] = acc[r][s] + bias[s];
    } else if (bid < 256) {
        // ---------------- kb-side gather GEMM: 8 rows per CTA -------------
        __shared__ float xs2[8][128];
        int idx0 = bid - 128;
        int b = idx0 >> 3, r0 = (idx0 & 7) * 8;

        for (int idx = tid; idx < 8 * 128; idx += 256) {
            int r = idx >> 7, e = idx & 127;
            int id = kb_ids[b * Nn + r0 + r];
            xs2[r][e] = kb_emb[(size_t)id * 128 + e];
        }
        __syncthreads();

        const float* wp[3];
        float bias[3];
        float* op[3];
#pragma unroll
        for (int s = 0; s < 3; s++) {
            int c = tid + 256 * s;
            if (c < 384) {
                wp[s] = fWwx + c; bias[s] = fbw[c];
                op[s] = g_Wg + ((size_t)b * Nn + r0) * 384 + c;
            } else {
                int c2 = c - 384;
                wp[s] = rWwx + c2; bias[s] = rbw[c2];
                op[s] = g_Wg + ((size_t)(Bb + b) * Nn + r0) * 384 + c2;
            }
        }

        float acc[8][3];
#pragma unroll
        for (int r = 0; r < 8; r++)
#pragma unroll
            for (int s = 0; s < 3; s++) acc[r][s] = 0.f;

        for (int e = 0; e < 128; e++) {
            float w0 = wp[0][(size_t)e * 384];
            float w1 = wp[1][(size_t)e * 384];
            float w2 = wp[2][(size_t)e * 384];
#pragma unroll
            for (int r = 0; r < 8; r++) {
                float x = xs2[r][e];
                acc[r][0] = fmaf(x, w0, acc[r][0]);
                acc[r][1] = fmaf(x, w1, acc[r][1]);
                acc[r][2] = fmaf(x, w2, acc[r][2]);
            }
        }

#pragma unroll
        for (int r = 0; r < 8; r++)
#pragma unroll
            for (int s = 0; s < 3; s++)
                op[s][(size_t)r * 384] = acc[r][s] + bias[s];
    } else {
        // ---------------- fp16 weight packing -----------------------------
        if (bid == 256 && tid == 0) g_crf_count = 0;   // reset for CRF reduce
        int bid2 = bid - 256;
        if (bid2 < 384) {
            int which = bid2 / 192;                    // 0 or 1 (Wwh f/r)
            int blockx = bid2 - which * 192;
            const float* in = which ? rWwh : fWwh;
            __half* out = g_Wwh16 + (size_t)which * 128 * 384;
            int idx = blockx * 256 + tid;
            if (idx < 128 * 384) {
                int j = idx / 384, k = idx - j * 384;
                out[((size_t)(j >> 3) * 384 + k) * 8 + (j & 7)] = __float2half(in[idx]);
            }
        } else {
            int bid3 = bid2 - 384;
            int which = bid3 / 64;                     // 0 or 1 (Wlc f/r)
            int blockx = bid3 - which * 64;
            const float* in = which ? rWlc : fWlc;
            __half* out = g_Wlc16 + (size_t)which * 128 * 128;
            int idx = blockx * 256 + tid;
            if (idx < 128 * 128) {
                int j = idx >> 7, k = idx & 127;
                out[((size_t)(j >> 3) * 128 + k) * 8 + (j & 7)] = __float2half(in[idx]);
            }
        }
    }
}

// ---------------------------------------------------------------------------
// Lattice LSTM (R13/R14 structure; bar5 removed — step_flag published after
// the top-of-step bar4, which already drains the previous update's stores).
// ---------------------------------------------------------------------------
#define NTHR 640

// smem BYTE offsets (all 16B aligned)
#define OFF_WWH   0                    // 98304
#define OFF_WLC   98304                // 32768
#define OFF_H32   131072               // 8*128 f32 = 4096
#define OFF_C32   135168               // 4096
#define OFF_H2    139264               // 8*128 fp16 = 2048
#define OFF_G     141312               // 512 f32 = 2048
#define OFF_CWS   143360               // 64*128 f32 = 32768
#define OFF_EWS   176128               // 32768
#define OFF_CW2   208896               // 64*128 fp16 = 16384
#define OFF_INT   225280               // 451 ints = 1804
#define SMEM_LAT  227084

__global__ void __launch_bounds__(NTHR, 1) lattice_kernel(
    const float* __restrict__ Wch_f, const float* __restrict__ Wch_r,
    const int* __restrict__ word_begin, const int* __restrict__ word_len,
    const int* __restrict__ seqlen)
{
    extern __shared__ char smraw[];
    __half* wwh_h   = (__half*)(smraw + OFF_WWH);
    __half* wlc_h   = (__half*)(smraw + OFF_WLC);
    float* h_ring   = (float*)(smraw + OFF_H32);
    float* c_ring   = (float*)(smraw + OFF_C32);
    __half* h2r     = (__half*)(smraw + OFF_H2);
    float* gates    = (float*)(smraw + OFF_G);
    float* cw_store = (float*)(smraw + OFF_CWS);
    float* ew_store = (float*)(smraw + OFF_EWS);
    __half* cw2_st  = (__half*)(smraw + OFF_CW2);
    int* ip        = (int*)(smraw + OFF_INT);
    int* w_beg     = ip;            // 64
    int* w_end     = ip + 64;       // 64
    int* el_start  = ip + 128;      // 129
    int* el_idx    = ip + 257;      // 64
    int* cur       = ip + 321;      // 128
    volatile int* step_flag  = (volatile int*)(ip + 449);
    volatile int* words_done = (volatile int*)(ip + 450);

    int dirb = blockIdx.x;
    int dir  = dirb / Bb;
    int b    = dirb - dir * Bb;
    int tid  = threadIdx.x;
    int sl   = seqlen[b];

    const float* Wch  = dir ? Wch_r : Wch_f;
    const float* Xg_b = g_Xg + (size_t)dirb * Ss * 512;
    const float* Xl_b = g_Xl + (size_t)dirb * Ss * 128;
    const float* Wg_b = g_Wg + (size_t)dirb * Nn * 384;

    // copy prepacked Wwh/Wlc fp16 into smem
    {
        const uint4* src = (const uint4*)(g_Wwh16 + (size_t)dir * 128 * 384);
        uint4* dst = (uint4*)wwh_h;
        for (int i = tid; i < 128 * 384 / 8; i += NTHR) dst[i] = src[i];
        const uint4* src2 = (const uint4*)(g_Wlc16 + (size_t)dir * 128 * 128);
        uint4* dst2 = (uint4*)wlc_h;
        for (int i = tid; i < 128 * 128 / 8; i += NTHR) dst2[i] = src2[i];
    }

    // ALL 128 Wch rows for column tid -> 64 half2 regs (char threads)
    __half2 wh[64];
    if (tid < 512) {
#pragma unroll
        for (int j = 0; j < 64; j++)
            wh[j] = __floats2half2_rn(Wch[(size_t)(2 * j) * 512 + tid],
                                      Wch[(size_t)(2 * j + 1) * 512 + tid]);
    }

    int t0 = dir ? (Ss - sl) : 0;
    int t1 = dir ? Ss : sl;

    if (tid < 128) {
        int s0 = (t0 & 7) * Hh;
        h_ring[s0 + tid] = 0.f;
        c_ring[s0 + tid] = 0.f;
        h2r[s0 + tid] = __float2half(0.f);
    }

    // zero masked feats rows
    for (int i = tid; i < (Ss - sl) * Hh; i += NTHR) {
        int row = sl + (i >> 7), col = i & 127;
        g_feats[((size_t)b * Ss + row) * (2 * Hh) + dir * Hh + col] = 0.f;
    }

    if (tid < Nn) {
        int bg = word_begin[b * Nn + tid];
        int ln = word_len[b * Nn + tid];
        int ef = min(bg + ln, Ss - 1);
        bool valid = ef < sl;
        if (dir == 0) {
            w_beg[tid] = bg;
            w_end[tid] = valid ? ef : -1;
        } else {
            w_beg[tid] = Ss - 1 - ef;
            w_end[tid] = valid ? (Ss - 1 - bg) : -1;
        }
    }
    __syncthreads();

    if (tid == 0) {
        for (int t = 0; t < Ss; t++) cur[t] = 0;
        for (int n = 0; n < Nn; n++) { int e = w_end[n]; if (e >= 0) cur[e]++; }
        el_start[0] = 0;
        for (int t = 0; t < Ss; t++) el_start[t + 1] = el_start[t] + cur[t];
        for (int t = 0; t < Ss; t++) cur[t] = el_start[t];
        for (int n = 0; n < Nn; n++) { int e = w_end[n]; if (e >= 0) el_idx[cur[e]++] = n; }
        *step_flag = t0;
        *words_done = 0;
    }
    __syncthreads();

    if (tid >= 512) {
        // ============ free-running word pipeline (all-HFMA2) ============
        int wt = tid - 512;
        const uint4* ww = (const uint4*)wwh_h;
        const uint4* wl = (const uint4*)wlc_h;
        const __half2 hz = __floats2half2_rn(0.f, 0.f);
        int total = el_start[Ss];
        for (int wv = 0; wv < total; wv++) {
            int n  = el_idx[wv];
            int bg = w_beg[n];
            int e  = w_end[n];
            if (*step_flag < bg) {
                do { __nanosleep(64); } while (*step_flag < bg);
            }
            __threadfence_block();
            int bgS = (bg & 7) * Hh;
            const uint4* hq = (const uint4*)(h2r + bgS);
            __half2 A[12];
#pragma unroll
            for (int i = 0; i < 12; i++) A[i] = hz;
#pragma unroll
            for (int j8 = 0; j8 < 16; j8++) {
                uint4 hv = hq[j8];
                int s = j8 & 3;
                hdot8(A[s],     hv, ww[j8 * 384 + wt]);
                hdot8(A[4 + s], hv, ww[j8 * 384 + wt + 128]);
                hdot8(A[8 + s], hv, ww[j8 * 384 + wt + 256]);
            }
            float acc0 = __ldg(Wg_b + (size_t)n * 384 + wt);
            float acc1 = __ldg(Wg_b + (size_t)n * 384 + wt + 128);
            float acc2 = __ldg(Wg_b + (size_t)n * 384 + wt + 256);
#pragma unroll
            for (int i = 0; i < 4; i++) {
                float2 v0 = __half22float2(A[i]);
                float2 v1 = __half22float2(A[4 + i]);
                float2 v2 = __half22float2(A[8 + i]);
                acc0 += v0.x + v0.y;
                acc1 += v1.x + v1.y;
                acc2 += v2.x + v2.y;
            }
            float cwv = sigf(acc1) * c_ring[bgS + wt] + sigf(acc0) * tanhfast(acc2);
            cw_store[n * 128 + wt] = cwv;
            cw2_st[n * 128 + wt] = __float2half(cwv);
            asm volatile("bar.sync 1, 128;" ::: "memory");
            const uint4* c2 = (const uint4*)(cw2_st + n * 128);
            __half2 Q0 = hz, Q1 = hz, Q2 = hz, Q3 = hz;
#pragma unroll
            for (int j8 = 0; j8 < 16; j8 += 4) {
                hdot8(Q0, c2[j8],     wl[j8 * 128 + wt]);
                hdot8(Q1, c2[j8 + 1], wl[(j8 + 1) * 128 + wt]);
                hdot8(Q2, c2[j8 + 2], wl[(j8 + 2) * 128 + wt]);
                hdot8(Q3, c2[j8 + 3], wl[(j8 + 3) * 128 + wt]);
            }
            float2 q0 = __half22float2(Q0);
            float2 q1 = __half22float2(Q1);
            float2 q2 = __half22float2(Q2);
            float2 q3 = __half22float2(Q3);
            float qsum = (q0.x + q0.y) + (q1.x + q1.y) + (q2.x + q2.y) + (q3.x + q3.y);
            float ew = __expf(sigf(__ldg(Xl_b + (size_t)e * 128 + wt) + qsum));
            ew_store[n * 128 + wt] = ew;
            asm volatile("bar.sync 1, 128;" ::: "memory");
            if (wt == 0) *words_done = wv + 1;
        }
    } else {
        // ================= step-locked char + update =================
        float xg = Xg_b[(size_t)t0 * 512 + tid];
        int gt = tid >> 7;
        const __half2 hz = __floats2half2_rn(0.f, 0.f);

        for (int t = t0; t < t1; t++) {
            int curS = (t & 7) * Hh;
            int nxtS = ((t + 1) & 7) * Hh;

            asm volatile("bar.sync 4, 512;" ::: "memory");   // state t ready (drains prev stores)
            if (tid == 128) *step_flag = t;                  // publish: slot t readable

            float xg_cur = xg;
            if (t + 1 < t1) xg = Xg_b[(size_t)(t + 1) * 512 + tid];

            const uint4* h2q = (const uint4*)(h2r + curS);
            __half2 a0 = hz, a1 = hz, a2 = hz, a3 = hz;
#pragma unroll
            for (int q = 0; q < 16; q++) {
                uint4 hv = h2q[q];
                a0 = __hfma2(u2h2(hv.x), wh[4 * q + 0], a0);
                a1 = __hfma2(u2h2(hv.y), wh[4 * q + 1], a1);
                a2 = __hfma2(u2h2(hv.z), wh[4 * q + 2], a2);
                a3 = __hfma2(u2h2(hv.w), wh[4 * q + 3], a3);
            }
            float2 f0 = __half22float2(a0);
            float2 f1 = __half22float2(a1);
            float2 f2 = __half22float2(a2);
            float2 f3 = __half22float2(a3);
            float gv = xg_cur + ((f0.x + f0.y) + (f1.x + f1.y))
                              + ((f2.x + f2.y) + (f3.x + f3.y));
            gates[tid] = (gt == 3) ? tanhfast(gv) : sigf(gv);
            asm volatile("bar.sync 4, 512;" ::: "memory");   // gates ready

            if (tid < 128) {
                int wls = el_start[t];
                int m = el_start[t + 1] - wls;
                float ig = gates[tid];
                float fg = gates[Hh + tid];
                float og = gates[2 * Hh + tid];
                float gg = gates[3 * Hh + tid];
                float cp = c_ring[curS + tid];
                float ct;
                if (m > 0) {
                    int target = wls + m;
                    if (*words_done < target) {
                        do { __nanosleep(32); } while (*words_done < target);
                    }
                    __threadfence_block();
                    float sew = 0.f, sewc = 0.f;
                    for (int wv = 0; wv < m; wv++) {
                        int n = el_idx[wls + wv];
                        float ew = ew_store[n * 128 + tid];
                        sew  += ew;
                        sewc += ew * cw_store[n * 128 + tid];
                    }
                    float ec = __expf(ig);
                    ct = __fdividef(ec * gg + sewc, ec + sew);
                } else {
                    ct = fg * cp + ig * gg;
                }
                float ht = og * tanhfast(ct);
                h_ring[nxtS + tid] = ht;
                c_ring[nxtS + tid] = ct;
                h2r[nxtS + tid] = __float2half(ht);
                int tt = (dir == 0) ? t : (Ss - 1 - t);
                g_feats[((size_t)b * Ss + tt) * (2 * Hh) + dir * Hh + tid] = ht;
            }
            // no bar5: next iteration's top bar4 orders the state stores
        }
    }
}

// ---------------------------------------------------------------------------
// Dense projection
// ---------------------------------------------------------------------------
__global__ void dense_kernel(const float* __restrict__ W, const float* __restrict__ bias)
{
    __shared__ float fs[8][2 * Hh];
    int row0 = blockIdx.x * 8;
    int tid = threadIdx.x;
    for (int idx = tid; idx < 8 * 2 * Hh; idx += 256) {
        int r = idx >> 8;
        int e = idx & 255;
        fs[r][e] = g_feats[(size_t)(row0 + r) * (2 * Hh) + e];
    }
    __syncthreads();
    int r = tid >> 5;
    int col = tid & 31;
    float acc = bias[col];
#pragma unroll 8
    for (int e = 0; e < 2 * Hh; e++) acc = fmaf(fs[r][e], W[e * Ll + col], acc);
    g_logits[(size_t)(row0 + r) * Ll + col] = acc;
}

// ---------------------------------------------------------------------------
// CRF with fused final reduction (last block sums and writes d_out)
// ---------------------------------------------------------------------------
__global__ void crf_kernel(const int* __restrict__ label,
                           const int* __restrict__ seqlen,
                           const float* __restrict__ T,
                           float* __restrict__ out)
{
    int b = blockIdx.x;
    int j = threadIdx.x;
    int sl = seqlen[b];
    const float* lg = g_logits + (size_t)b * Ss * Ll;
    const int*   lab = label + b * Ss;

    float Tc[32];
#pragma unroll
    for (int i = 0; i < 32; i++) Tc[i] = T[i * Ll + j];

    float gold = 0.f;
    for (int t = j; t < Ss; t += 32)
        if (t < sl) gold += lg[t * Ll + lab[t]];
    for (int t = j + 1; t < Ss; t += 32)
        if (t < sl) gold += T[lab[t - 1] * Ll + lab[t]];
#pragma unroll
    for (int o = 16; o; o >>= 1) gold += __shfl_xor_sync(0xffffffffu, gold, o);

    float alpha = lg[j];
    for (int t = 1; t < Ss; t++) {
        float vmax = -1e30f;
#pragma unroll
        for (int i = 0; i < 32; i++) {
            float ai = __shfl_sync(0xffffffffu, alpha, i);
            vmax = fmaxf(vmax, ai + Tc[i]);
        }
        float s = 0.f;
#pragma unroll
        for (int i = 0; i < 32; i++) {
            float ai = __shfl_sync(0xffffffffu, alpha, i);
            s += __expf(ai + Tc[i] - vmax);
        }
        float na = vmax + __logf(s) + lg[(size_t)t * Ll + j];
        if (t < sl) alpha = na;
    }
    float m2 = alpha;
#pragma unroll
    for (int o = 16; o; o >>= 1) m2 = fmaxf(m2, __shfl_xor_sync(0xffffffffu, m2, o));
    float s2 = __expf(alpha - m2);
#pragma unroll
    for (int o = 16; o; o >>= 1) s2 += __shfl_xor_sync(0xffffffffu, s2, o);

    if (j == 0) {
        g_pb[b] = (m2 + __logf(s2)) - gold;
        __threadfence();
        int done = atomicAdd(&g_crf_count, 1);
        if (done == Bb - 1) {
            float s = 0.f;
#pragma unroll
            for (int i = 0; i < Bb; i++) s += g_pb[i];
            out[0] = s / (float)Bb;
        }
    }
}

// ---------------------------------------------------------------------------
// Launch
// ---------------------------------------------------------------------------
extern "C" void kernel_launch(void* const* d_in, const int* in_sizes, int n_in,
                              void* d_out, int out_size)
{
    const int* char_ids = (const int*)d_in[0];
    const int* kb_ids   = (const int*)d_in[1];
    const int* wbeg     = (const int*)d_in[2];
    const int* wlen     = (const int*)d_in[3];
    const int* label    = (const int*)d_in[4];
    const int* slen     = (const int*)d_in[5];
    const float* char_emb = (const float*)d_in[6];
    const float* kb_emb   = (const float*)d_in[7];
    const float* dense_W  = (const float*)d_in[8];
    const float* dense_b  = (const float*)d_in[9];
    const float* crf_T    = (const float*)d_in[10];

    const float* f_Wcx = (const float*)d_in[11];
    const float* f_Wch = (const float*)d_in[12];
    const float* f_bc  = (const float*)d_in[13];
    const float* f_Wwx = (const float*)d_in[14];
    const float* f_Wwh = (const float*)d_in[15];
    const float* f_bw  = (const float*)d_in[16];
    const float* f_Wlx = (const float*)d_in[17];
    const float* f_Wlc = (const float*)d_in[18];
    const float* f_bl  = (const float*)d_in[19];

    const float* r_Wcx = (const float*)d_in[20];
    const float* r_Wch = (const float*)d_in[21];
    const float* r_bc  = (const float*)d_in[22];
    const float* r_Wwx = (const float*)d_in[23];
    const float* r_Wwh = (const float*)d_in[24];
    const float* r_bw  = (const float*)d_in[25];
    const float* r_Wlx = (const float*)d_in[26];
    const float* r_Wlc = (const float*)d_in[27];
    const float* r_bl  = (const float*)d_in[28];

    front_kernel<<<768, 256>>>(char_emb, char_ids, kb_emb, kb_ids,
        f_Wcx, r_Wcx, f_Wlx, r_Wlx, f_bc, r_bc, f_bl, r_bl,
        f_Wwx, r_Wwx, f_bw, r_bw, f_Wwh, r_Wwh, f_Wlc, r_Wlc);

    cudaFuncSetAttribute(lattice_kernel, cudaFuncAttributeMaxDynamicSharedMemorySize, SMEM_LAT);
    lattice_kernel<<<2 * Bb, NTHR, SMEM_LAT>>>(f_Wch, r_Wch, wbeg, wlen, slen);

    dense_kernel<<<(Bb * Ss) / 8, 256>>>(dense_W, dense_b);
    crf_kernel<<<Bb, 32>>>(label, slen, crf_T, (float*)d_out);
}

// round 16
// speedup vs baseline: 1.3418x; 1.0372x over previous
#include <cuda_runtime.h>
#include <cuda_fp16.h>
#include <math.h>

#define Bb 16
#define Ss 128
#define Nn 64
#define Ee 128
#define Hh 128
#define Ll 32

// ---------------------------------------------------------------------------
// Device-global scratch
// ---------------------------------------------------------------------------
__device__ float g_Xg[(size_t)2 * Bb * Ss * 4 * Hh];   // (dir,b,t,512)
__device__ float g_Xl[(size_t)2 * Bb * Ss * Hh];       // (dir,b,t,128)
__device__ float g_Wg[(size_t)2 * Bb * Nn * 3 * Hh];   // (dir,b,n,384)
__device__ __half g_Wwh16[(size_t)2 * 128 * 384];      // (dir, (j8*384+k)*8+i)
__device__ __half g_Wlc16[(size_t)2 * 128 * 128];      // (dir, (j8*128+k)*8+i)
__device__ float g_feats[(size_t)Bb * Ss * 2 * Hh];
__device__ float g_logits[(size_t)Bb * Ss * Ll];
__device__ float g_pb[Bb];
__device__ int   g_crf_count;

// fast transcendentals (~2 ulp; tolerance is 1e-3)
__device__ __forceinline__ float sigf(float x) {
    return __fdividef(1.f, 1.f + __expf(-x));
}
__device__ __forceinline__ float tanhfast(float x) {
    return 1.f - 2.f * __fdividef(1.f, __expf(2.f * x) + 1.f);
}

__device__ __forceinline__ __half2 u2h2(unsigned int v) {
    return *reinterpret_cast<const __half2*>(&v);
}

// 4 packed HFMA2: accumulate 8 fp16 products (h quad × w quad) into acc
__device__ __forceinline__ void hdot8(__half2& acc, uint4 h, uint4 w) {
    acc = __hfma2(u2h2(h.x), u2h2(w.x), acc);
    acc = __hfma2(u2h2(h.y), u2h2(w.y), acc);
    acc = __hfma2(u2h2(h.z), u2h2(w.z), acc);
    acc = __hfma2(u2h2(h.w), u2h2(w.w), acc);
}

// ---------------------------------------------------------------------------
// Fused front kernel (unchanged from R15)
// ---------------------------------------------------------------------------
__global__ void __launch_bounds__(256) front_kernel(
    const float* __restrict__ char_emb, const int* __restrict__ char_ids,
    const float* __restrict__ kb_emb,   const int* __restrict__ kb_ids,
    const float* __restrict__ fWcx, const float* __restrict__ rWcx,
    const float* __restrict__ fWlx, const float* __restrict__ rWlx,
    const float* __restrict__ fbc, const float* __restrict__ rbc,
    const float* __restrict__ fbl, const float* __restrict__ rbl,
    const float* __restrict__ fWwx, const float* __restrict__ rWwx,
    const float* __restrict__ fbw, const float* __restrict__ rbw,
    const float* __restrict__ fWwh, const float* __restrict__ rWwh,
    const float* __restrict__ fWlc, const float* __restrict__ rWlc)
{
    int bid = blockIdx.x;
    int tid = threadIdx.x;

    if (bid < 128) {
        __shared__ float xs[16][128];
        int b = bid >> 3, r0 = (bid & 7) * 16;

        for (int idx = tid; idx < 16 * 128; idx += 256) {
            int r = idx >> 7, e = idx & 127;
            int id = char_ids[b * Ss + r0 + r];
            xs[r][e] = char_emb[(size_t)id * 128 + e];
        }
        __syncthreads();

        const float* wp[5];
        float bias[5];
        float* op[5];
        int ostep[5];

        wp[0] = fWcx + tid;        bias[0] = fbc[tid];
        wp[1] = fWcx + tid + 256;  bias[1] = fbc[tid + 256];
        op[0] = g_Xg + ((size_t)b * Ss + r0) * 512 + tid;
        op[1] = op[0] + 256;
        ostep[0] = ostep[1] = 512;
        wp[2] = rWcx + tid;        bias[2] = rbc[tid];
        wp[3] = rWcx + tid + 256;  bias[3] = rbc[tid + 256];
        op[2] = g_Xg + ((size_t)(Bb + b) * Ss + (Ss - 1 - r0)) * 512 + tid;
        op[3] = op[2] + 256;
        ostep[2] = ostep[3] = -512;
        if (tid < 128) {
            wp[4] = fWlx + tid; bias[4] = fbl[tid];
            op[4] = g_Xl + ((size_t)b * Ss + r0) * 128 + tid;
            ostep[4] = 128;
        } else {
            int c = tid - 128;
            wp[4] = rWlx + c; bias[4] = rbl[c];
            op[4] = g_Xl + ((size_t)(Bb + b) * Ss + (Ss - 1 - r0)) * 128 + c;
            ostep[4] = -128;
        }

        float acc[16][5];
#pragma unroll
        for (int r = 0; r < 16; r++)
#pragma unroll
            for (int s = 0; s < 5; s++) acc[r][s] = 0.f;

        for (int e = 0; e < 128; e++) {
            float w0 = wp[0][(size_t)e * 512];
            float w1 = wp[1][(size_t)e * 512];
            float w2 = wp[2][(size_t)e * 512];
            float w3 = wp[3][(size_t)e * 512];
            float w4 = wp[4][(size_t)e * 128];
#pragma unroll
            for (int r = 0; r < 16; r++) {
                float x = xs[r][e];
                acc[r][0] = fmaf(x, w0, acc[r][0]);
                acc[r][1] = fmaf(x, w1, acc[r][1]);
                acc[r][2] = fmaf(x, w2, acc[r][2]);
                acc[r][3] = fmaf(x, w3, acc[r][3]);
                acc[r][4] = fmaf(x, w4, acc[r][4]);
            }
        }

#pragma unroll
        for (int r = 0; r < 16; r++)
#pragma unroll
            for (int s = 0; s < 5; s++)
                op[s][(long)r * ostep[s]] = acc[r][s] + bias[s];
    } else if (bid < 256) {
        __shared__ float xs2[8][128];
        int idx0 = bid - 128;
        int b = idx0 >> 3, r0 = (idx0 & 7) * 8;

        for (int idx = tid; idx < 8 * 128; idx += 256) {
            int r = idx >> 7, e = idx & 127;
            int id = kb_ids[b * Nn + r0 + r];
            xs2[r][e] = kb_emb[(size_t)id * 128 + e];
        }
        __syncthreads();

        const float* wp[3];
        float bias[3];
        float* op[3];
#pragma unroll
        for (int s = 0; s < 3; s++) {
            int c = tid + 256 * s;
            if (c < 384) {
                wp[s] = fWwx + c; bias[s] = fbw[c];
                op[s] = g_Wg + ((size_t)b * Nn + r0) * 384 + c;
            } else {
                int c2 = c - 384;
                wp[s] = rWwx + c2; bias[s] = rbw[c2];
                op[s] = g_Wg + ((size_t)(Bb + b) * Nn + r0) * 384 + c2;
            }
        }

        float acc[8][3];
#pragma unroll
        for (int r = 0; r < 8; r++)
#pragma unroll
            for (int s = 0; s < 3; s++) acc[r][s] = 0.f;

        for (int e = 0; e < 128; e++) {
            float w0 = wp[0][(size_t)e * 384];
            float w1 = wp[1][(size_t)e * 384];
            float w2 = wp[2][(size_t)e * 384];
#pragma unroll
            for (int r = 0; r < 8; r++) {
                float x = xs2[r][e];
                acc[r][0] = fmaf(x, w0, acc[r][0]);
                acc[r][1] = fmaf(x, w1, acc[r][1]);
                acc[r][2] = fmaf(x, w2, acc[r][2]);
            }
        }

#pragma unroll
        for (int r = 0; r < 8; r++)
#pragma unroll
            for (int s = 0; s < 3; s++)
                op[s][(size_t)r * 384] = acc[r][s] + bias[s];
    } else {
        if (bid == 256 && tid == 0) g_crf_count = 0;
        int bid2 = bid - 256;
        if (bid2 < 384) {
            int which = bid2 / 192;
            int blockx = bid2 - which * 192;
            const float* in = which ? rWwh : fWwh;
            __half* out = g_Wwh16 + (size_t)which * 128 * 384;
            int idx = blockx * 256 + tid;
            if (idx < 128 * 384) {
                int j = idx / 384, k = idx - j * 384;
                out[((size_t)(j >> 3) * 384 + k) * 8 + (j & 7)] = __float2half(in[idx]);
            }
        } else {
            int bid3 = bid2 - 384;
            int which = bid3 / 64;
            int blockx = bid3 - which * 64;
            const float* in = which ? rWlc : fWlc;
            __half* out = g_Wlc16 + (size_t)which * 128 * 128;
            int idx = blockx * 256 + tid;
            if (idx < 128 * 128) {
                int j = idx >> 7, k = idx & 127;
                out[((size_t)(j >> 3) * 128 + k) * 8 + (j & 7)] = __float2half(in[idx]);
            }
        }
    }
}

// ---------------------------------------------------------------------------
// Lattice LSTM (unchanged from R15)
// ---------------------------------------------------------------------------
#define NTHR 640

#define OFF_WWH   0
#define OFF_WLC   98304
#define OFF_H32   131072
#define OFF_C32   135168
#define OFF_H2    139264
#define OFF_G     141312
#define OFF_CWS   143360
#define OFF_EWS   176128
#define OFF_CW2   208896
#define OFF_INT   225280
#define SMEM_LAT  227084

__global__ void __launch_bounds__(NTHR, 1) lattice_kernel(
    const float* __restrict__ Wch_f, const float* __restrict__ Wch_r,
    const int* __restrict__ word_begin, const int* __restrict__ word_len,
    const int* __restrict__ seqlen)
{
    extern __shared__ char smraw[];
    __half* wwh_h   = (__half*)(smraw + OFF_WWH);
    __half* wlc_h   = (__half*)(smraw + OFF_WLC);
    float* h_ring   = (float*)(smraw + OFF_H32);
    float* c_ring   = (float*)(smraw + OFF_C32);
    __half* h2r     = (__half*)(smraw + OFF_H2);
    float* gates    = (float*)(smraw + OFF_G);
    float* cw_store = (float*)(smraw + OFF_CWS);
    float* ew_store = (float*)(smraw + OFF_EWS);
    __half* cw2_st  = (__half*)(smraw + OFF_CW2);
    int* ip        = (int*)(smraw + OFF_INT);
    int* w_beg     = ip;
    int* w_end     = ip + 64;
    int* el_start  = ip + 128;
    int* el_idx    = ip + 257;
    int* cur       = ip + 321;
    volatile int* step_flag  = (volatile int*)(ip + 449);
    volatile int* words_done = (volatile int*)(ip + 450);

    int dirb = blockIdx.x;
    int dir  = dirb / Bb;
    int b    = dirb - dir * Bb;
    int tid  = threadIdx.x;
    int sl   = seqlen[b];

    const float* Wch  = dir ? Wch_r : Wch_f;
    const float* Xg_b = g_Xg + (size_t)dirb * Ss * 512;
    const float* Xl_b = g_Xl + (size_t)dirb * Ss * 128;
    const float* Wg_b = g_Wg + (size_t)dirb * Nn * 384;

    {
        const uint4* src = (const uint4*)(g_Wwh16 + (size_t)dir * 128 * 384);
        uint4* dst = (uint4*)wwh_h;
        for (int i = tid; i < 128 * 384 / 8; i += NTHR) dst[i] = src[i];
        const uint4* src2 = (const uint4*)(g_Wlc16 + (size_t)dir * 128 * 128);
        uint4* dst2 = (uint4*)wlc_h;
        for (int i = tid; i < 128 * 128 / 8; i += NTHR) dst2[i] = src2[i];
    }

    __half2 wh[64];
    if (tid < 512) {
#pragma unroll
        for (int j = 0; j < 64; j++)
            wh[j] = __floats2half2_rn(Wch[(size_t)(2 * j) * 512 + tid],
                                      Wch[(size_t)(2 * j + 1) * 512 + tid]);
    }

    int t0 = dir ? (Ss - sl) : 0;
    int t1 = dir ? Ss : sl;

    if (tid < 128) {
        int s0 = (t0 & 7) * Hh;
        h_ring[s0 + tid] = 0.f;
        c_ring[s0 + tid] = 0.f;
        h2r[s0 + tid] = __float2half(0.f);
    }

    for (int i = tid; i < (Ss - sl) * Hh; i += NTHR) {
        int row = sl + (i >> 7), col = i & 127;
        g_feats[((size_t)b * Ss + row) * (2 * Hh) + dir * Hh + col] = 0.f;
    }

    if (tid < Nn) {
        int bg = word_begin[b * Nn + tid];
        int ln = word_len[b * Nn + tid];
        int ef = min(bg + ln, Ss - 1);
        bool valid = ef < sl;
        if (dir == 0) {
            w_beg[tid] = bg;
            w_end[tid] = valid ? ef : -1;
        } else {
            w_beg[tid] = Ss - 1 - ef;
            w_end[tid] = valid ? (Ss - 1 - bg) : -1;
        }
    }
    __syncthreads();

    if (tid == 0) {
        for (int t = 0; t < Ss; t++) cur[t] = 0;
        for (int n = 0; n < Nn; n++) { int e = w_end[n]; if (e >= 0) cur[e]++; }
        el_start[0] = 0;
        for (int t = 0; t < Ss; t++) el_start[t + 1] = el_start[t] + cur[t];
        for (int t = 0; t < Ss; t++) cur[t] = el_start[t];
        for (int n = 0; n < Nn; n++) { int e = w_end[n]; if (e >= 0) el_idx[cur[e]++] = n; }
        *step_flag = t0;
        *words_done = 0;
    }
    __syncthreads();

    if (tid >= 512) {
        int wt = tid - 512;
        const uint4* ww = (const uint4*)wwh_h;
        const uint4* wl = (const uint4*)wlc_h;
        const __half2 hz = __floats2half2_rn(0.f, 0.f);
        int total = el_start[Ss];
        for (int wv = 0; wv < total; wv++) {
            int n  = el_idx[wv];
            int bg = w_beg[n];
            int e  = w_end[n];
            if (*step_flag < bg) {
                do { __nanosleep(64); } while (*step_flag < bg);
            }
            __threadfence_block();
            int bgS = (bg & 7) * Hh;
            const uint4* hq = (const uint4*)(h2r + bgS);
            __half2 A[12];
#pragma unroll
            for (int i = 0; i < 12; i++) A[i] = hz;
#pragma unroll
            for (int j8 = 0; j8 < 16; j8++) {
                uint4 hv = hq[j8];
                int s = j8 & 3;
                hdot8(A[s],     hv, ww[j8 * 384 + wt]);
                hdot8(A[4 + s], hv, ww[j8 * 384 + wt + 128]);
                hdot8(A[8 + s], hv, ww[j8 * 384 + wt + 256]);
            }
            float acc0 = __ldg(Wg_b + (size_t)n * 384 + wt);
            float acc1 = __ldg(Wg_b + (size_t)n * 384 + wt + 128);
            float acc2 = __ldg(Wg_b + (size_t)n * 384 + wt + 256);
#pragma unroll
            for (int i = 0; i < 4; i++) {
                float2 v0 = __half22float2(A[i]);
                float2 v1 = __half22float2(A[4 + i]);
                float2 v2 = __half22float2(A[8 + i]);
                acc0 += v0.x + v0.y;
                acc1 += v1.x + v1.y;
                acc2 += v2.x + v2.y;
            }
            float cwv = sigf(acc1) * c_ring[bgS + wt] + sigf(acc0) * tanhfast(acc2);
            cw_store[n * 128 + wt] = cwv;
            cw2_st[n * 128 + wt] = __float2half(cwv);
            asm volatile("bar.sync 1, 128;" ::: "memory");
            const uint4* c2 = (const uint4*)(cw2_st + n * 128);
            __half2 Q0 = hz, Q1 = hz, Q2 = hz, Q3 = hz;
#pragma unroll
            for (int j8 = 0; j8 < 16; j8 += 4) {
                hdot8(Q0, c2[j8],     wl[j8 * 128 + wt]);
                hdot8(Q1, c2[j8 + 1], wl[(j8 + 1) * 128 + wt]);
                hdot8(Q2, c2[j8 + 2], wl[(j8 + 2) * 128 + wt]);
                hdot8(Q3, c2[j8 + 3], wl[(j8 + 3) * 128 + wt]);
            }
            float2 q0 = __half22float2(Q0);
            float2 q1 = __half22float2(Q1);
            float2 q2 = __half22float2(Q2);
            float2 q3 = __half22float2(Q3);
            float qsum = (q0.x + q0.y) + (q1.x + q1.y) + (q2.x + q2.y) + (q3.x + q3.y);
            float ew = __expf(sigf(__ldg(Xl_b + (size_t)e * 128 + wt) + qsum));
            ew_store[n * 128 + wt] = ew;
            asm volatile("bar.sync 1, 128;" ::: "memory");
            if (wt == 0) *words_done = wv + 1;
        }
    } else {
        float xg = Xg_b[(size_t)t0 * 512 + tid];
        int gt = tid >> 7;
        const __half2 hz = __floats2half2_rn(0.f, 0.f);

        for (int t = t0; t < t1; t++) {
            int curS = (t & 7) * Hh;
            int nxtS = ((t + 1) & 7) * Hh;

            asm volatile("bar.sync 4, 512;" ::: "memory");
            if (tid == 128) *step_flag = t;

            float xg_cur = xg;
            if (t + 1 < t1) xg = Xg_b[(size_t)(t + 1) * 512 + tid];

            const uint4* h2q = (const uint4*)(h2r + curS);
            __half2 a0 = hz, a1 = hz, a2 = hz, a3 = hz;
#pragma unroll
            for (int q = 0; q < 16; q++) {
                uint4 hv = h2q[q];
                a0 = __hfma2(u2h2(hv.x), wh[4 * q + 0], a0);
                a1 = __hfma2(u2h2(hv.y), wh[4 * q + 1], a1);
                a2 = __hfma2(u2h2(hv.z), wh[4 * q + 2], a2);
                a3 = __hfma2(u2h2(hv.w), wh[4 * q + 3], a3);
            }
            float2 f0 = __half22float2(a0);
            float2 f1 = __half22float2(a1);
            float2 f2 = __half22float2(a2);
            float2 f3 = __half22float2(a3);
            float gv = xg_cur + ((f0.x + f0.y) + (f1.x + f1.y))
                              + ((f2.x + f2.y) + (f3.x + f3.y));
            gates[tid] = (gt == 3) ? tanhfast(gv) : sigf(gv);
            asm volatile("bar.sync 4, 512;" ::: "memory");

            if (tid < 128) {
                int wls = el_start[t];
                int m = el_start[t + 1] - wls;
                float ig = gates[tid];
                float fg = gates[Hh + tid];
                float og = gates[2 * Hh + tid];
                float gg = gates[3 * Hh + tid];
                float cp = c_ring[curS + tid];
                float ct;
                if (m > 0) {
                    int target = wls + m;
                    if (*words_done < target) {
                        do { __nanosleep(32); } while (*words_done < target);
                    }
                    __threadfence_block();
                    float sew = 0.f, sewc = 0.f;
                    for (int wv = 0; wv < m; wv++) {
                        int n = el_idx[wls + wv];
                        float ew = ew_store[n * 128 + tid];
                        sew  += ew;
                        sewc += ew * cw_store[n * 128 + tid];
                    }
                    float ec = __expf(ig);
                    ct = __fdividef(ec * gg + sewc, ec + sew);
                } else {
                    ct = fg * cp + ig * gg;
                }
                float ht = og * tanhfast(ct);
                h_ring[nxtS + tid] = ht;
                c_ring[nxtS + tid] = ct;
                h2r[nxtS + tid] = __float2half(ht);
                int tt = (dir == 0) ? t : (Ss - 1 - t);
                g_feats[((size_t)b * Ss + tt) * (2 * Hh) + dir * Hh + tid] = ht;
            }
        }
    }
}

// ---------------------------------------------------------------------------
// Dense projection (unchanged)
// ---------------------------------------------------------------------------
__global__ void dense_kernel(const float* __restrict__ W, const float* __restrict__ bias)
{
    __shared__ float fs[8][2 * Hh];
    int row0 = blockIdx.x * 8;
    int tid = threadIdx.x;
    for (int idx = tid; idx < 8 * 2 * Hh; idx += 256) {
        int r = idx >> 8;
        int e = idx & 255;
        fs[r][e] = g_feats[(size_t)(row0 + r) * (2 * Hh) + e];
    }
    __syncthreads();
    int r = tid >> 5;
    int col = tid & 31;
    float acc = bias[col];
#pragma unroll 8
    for (int e = 0; e < 2 * Hh; e++) acc = fmaf(fs[r][e], W[e * Ll + col], acc);
    g_logits[(size_t)(row0 + r) * Ll + col] = acc;
}

// ---------------------------------------------------------------------------
// Parallel CRF: 1024 threads per batch. Thread (warp j, lane i) owns T[i][j].
// Per step: one exp per thread, warp-reduce over i, lane0 log+store.
// Running renormalization (subtract alpha[0], accumulate offset) replaces the
// per-j max — exact shift identity. Fused final reduction.
// ---------------------------------------------------------------------------
__global__ void __launch_bounds__(1024) crf_kernel(
    const int* __restrict__ label, const int* __restrict__ seqlen,
    const float* __restrict__ T, float* __restrict__ out)
{
    __shared__ float lgs[Ss * Ll];    // 16 KB
    __shared__ float abuf[2][Ll];
    __shared__ float gold_sm[Ss];

    int b = blockIdx.x;
    int tid = threadIdx.x;
    int j = tid >> 5;      // output label (warp)
    int lane = tid & 31;   // input label i
    int sl = seqlen[b];
    const int* lab = label + b * Ss;

    // preload logits
    {
        const float* lg = g_logits + (size_t)b * Ss * Ll;
        for (int i = tid; i < Ss * Ll; i += 1024) lgs[i] = lg[i];
    }
    float Tc = T[lane * Ll + j];

    // gold contributions in parallel (one thread per t)
    if (tid < Ss) {
        int t = tid;
        float gv = 0.f;
        if (t < sl) {
            gv = lgs[t * Ll + lab[t]];
            if (t >= 1) gv += T[lab[t - 1] * Ll + lab[t]];
        }
        gold_sm[t] = gv;
    }
    if (tid < Ll) abuf[0][tid] = lgs[tid];
    __syncthreads();

    float off = 0.f;
    int p = 0;
    for (int t = 1; t < Ss; t++) {
        float av = abuf[p][lane];
        float ref = __shfl_sync(0xffffffffu, av, 0);   // renormalizer
        float e = __expf(av - ref + Tc);
#pragma unroll
        for (int o = 16; o; o >>= 1) e += __shfl_xor_sync(0xffffffffu, e, o);
        off += ref;
        if (lane == 0) {
            float na = __logf(e) + lgs[t * Ll + j];
            abuf[p ^ 1][j] = (t < sl) ? na : (abuf[p][j] - ref);
        }
        p ^= 1;
        __syncthreads();
    }

    // final: warp 0 reduces logZ and gold
    if (tid < 32) {
        float a = abuf[p][lane];
        float m2 = a;
#pragma unroll
        for (int o = 16; o; o >>= 1) m2 = fmaxf(m2, __shfl_xor_sync(0xffffffffu, m2, o));
        float s2 = __expf(a - m2);
#pragma unroll
        for (int o = 16; o; o >>= 1) s2 += __shfl_xor_sync(0xffffffffu, s2, o);
        float g = gold_sm[lane] + gold_sm[lane + 32] + gold_sm[lane + 64] + gold_sm[lane + 96];
#pragma unroll
        for (int o = 16; o; o >>= 1) g += __shfl_xor_sync(0xffffffffu, g, o);
        if (lane == 0) {
            g_pb[b] = (m2 + __logf(s2) + off) - g;
            __threadfence();
            int done = atomicAdd(&g_crf_count, 1);
            if (done == Bb - 1) {
                float s = 0.f;
#pragma unroll
                for (int i = 0; i < Bb; i++) s += g_pb[i];
                out[0] = s / (float)Bb;
            }
        }
    }
}

// ---------------------------------------------------------------------------
// Launch
// ---------------------------------------------------------------------------
extern "C" void kernel_launch(void* const* d_in, const int* in_sizes, int n_in,
                              void* d_out, int out_size)
{
    const int* char_ids = (const int*)d_in[0];
    const int* kb_ids   = (const int*)d_in[1];
    const int* wbeg     = (const int*)d_in[2];
    const int* wlen     = (const int*)d_in[3];
    const int* label    = (const int*)d_in[4];
    const int* slen     = (const int*)d_in[5];
    const float* char_emb = (const float*)d_in[6];
    const float* kb_emb   = (const float*)d_in[7];
    const float* dense_W  = (const float*)d_in[8];
    const float* dense_b  = (const float*)d_in[9];
    const float* crf_T    = (const float*)d_in[10];

    const float* f_Wcx = (const float*)d_in[11];
    const float* f_Wch = (const float*)d_in[12];
    const float* f_bc  = (const float*)d_in[13];
    const float* f_Wwx = (const float*)d_in[14];
    const float* f_Wwh = (const float*)d_in[15];
    const float* f_bw  = (const float*)d_in[16];
    const float* f_Wlx = (const float*)d_in[17];
    const float* f_Wlc = (const float*)d_in[18];
    const float* f_bl  = (const float*)d_in[19];

    const float* r_Wcx = (const float*)d_in[20];
    const float* r_Wch = (const float*)d_in[21];
    const float* r_bc  = (const float*)d_in[22];
    const float* r_Wwx = (const float*)d_in[23];
    const float* r_Wwh = (const float*)d_in[24];
    const float* r_bw  = (const float*)d_in[25];
    const float* r_Wlx = (const float*)d_in[26];
    const float* r_Wlc = (const float*)d_in[27];
    const float* r_bl  = (const float*)d_in[28];

    front_kernel<<<768, 256>>>(char_emb, char_ids, kb_emb, kb_ids,
        f_Wcx, r_Wcx, f_Wlx, r_Wlx, f_bc, r_bc, f_bl, r_bl,
        f_Wwx, r_Wwx, f_bw, r_bw, f_Wwh, r_Wwh, f_Wlc, r_Wlc);

    cudaFuncSetAttribute(lattice_kernel, cudaFuncAttributeMaxDynamicSharedMemorySize, SMEM_LAT);
    lattice_kernel<<<2 * Bb, NTHR, SMEM_LAT>>>(f_Wch, r_Wch, wbeg, wlen, slen);

    dense_kernel<<<(Bb * Ss) / 8, 256>>>(dense_W, dense_b);
    crf_kernel<<<Bb, 1024>>>(label, slen, crf_T, (float*)d_out);
}